// round 1
// baseline (speedup 1.0000x reference)
#include <cuda_runtime.h>
#include <math.h>

// ---------------------------------------------------------------------------
// Problem constants
// B=64, S=64, T=64, STEPS=32, E=512, H=512, G=256, V=32000
// ---------------------------------------------------------------------------
#define NB   64
#define NS   64
#define NT   64
#define NSTEPS 32
#define NE   512
#define NH   512
#define NG   256
#define NV   32000
#define H4   2048
#define H2   1024
#define H3   1536
#define CIW  3328   // E + 2H + 2H + G + H

// ---------------------------------------------------------------------------
// Scratch (device globals; no allocations allowed)
// ---------------------------------------------------------------------------
__device__ float d_src_e[NS*NB*NE];        // time-major [s][b][e]
__device__ float d_rat_e[NS*NB*NE];
__device__ float d_tgt_e[NT*NB*NE];        // [t][b][e]
__device__ float d_Xw[4][NS*NB*H4];        // x@Wih + b per lstm {srcF,srcB,ratF,ratB}
__device__ float d_hbuf[2][4][NB*NH];      // ping-pong h
__device__ float d_cbuf[4][NB*NH];
__device__ float d_enc[2][NB*NS*H2];       // [b][s][2H]; 0=src 1=rat
__device__ float d_P[2][NB*NS*H3];         // enc_out @ W1[:2H] + b1
__device__ float d_q[NB*H3];               // h @ W1[2H:]
__device__ float d_Abuf[2][NSTEPS*NB*H2];  // attention outputs A, Ar
__device__ float d_Dbuf[NSTEPS*NB*NH];     // decoder h per step
__device__ float d_tgtW[NSTEPS*NB*H4];     // tgt_e @ dec_Wih[:E] + dec_b
__device__ float d_hdec[2][NB*NH];
__device__ float d_cdec[NB*NH];
__device__ float d_ci[(size_t)NB*NT*CIW];
__device__ float d_hid[(size_t)NB*NT*H2];

__device__ __forceinline__ float sigf(float x) { return 1.f / (1.f + expf(-x)); }

// ---------------------------------------------------------------------------
// Zero / init kernels
// ---------------------------------------------------------------------------
__global__ void zero_state_kernel() {
    int i = blockIdx.x * 256 + threadIdx.x;
    if (i < 2*4*NB*NH) ((float*)d_hbuf)[i] = 0.f;
    if (i < 4*NB*NH)   ((float*)d_cbuf)[i] = 0.f;
}

__global__ void init_dec_state_kernel() {
    int i = blockIdx.x * 256 + threadIdx.x;   // 32768 elems
    // after 64 encoder steps, current h lives in buffer (64&1)==0, lstm 0 = src fwd
    d_hdec[0][i] = d_hbuf[0][0][i];
    d_cdec[i]    = d_cbuf[0][i];
}

// ---------------------------------------------------------------------------
// Embedding gather: writes time-major [s][b][e]
// ---------------------------------------------------------------------------
__global__ void gather_kernel(const int* __restrict__ src_ids,
                              const int* __restrict__ tgt_ids,
                              const int* __restrict__ rat_ids,
                              const float* __restrict__ src_emb,
                              const float* __restrict__ tgt_emb) {
    int tok = blockIdx.x;          // s*64 + b
    int set = blockIdx.y;          // 0 src, 1 rat, 2 tgt
    int s = tok >> 6, b = tok & 63;
    int id;
    const float* emb;
    float* out;
    if (set == 0)      { id = src_ids[b*NS + s]; emb = src_emb; out = d_src_e; }
    else if (set == 1) { id = rat_ids[b*NS + s]; emb = src_emb; out = d_rat_e; }
    else               { id = tgt_ids[b*NT + s]; emb = tgt_emb; out = d_tgt_e; }
    const float* row = emb + (size_t)id * NE;
    float* dst = out + (size_t)tok * NE;
    for (int e = threadIdx.x; e < NE; e += 256) dst[e] = row[e];
}

// ---------------------------------------------------------------------------
// Generic fp32 GEMM: C[M,N] = A[M,K] @ B[K,N] (+bias) (+relu)
// BM=BN=128, BK=16, 256 threads, 8x8 microtile, float4 paths.
// Requires N % 128 == 0, K % 16 == 0. M arbitrary (guarded).
// ---------------------------------------------------------------------------
__global__ void __launch_bounds__(256)
gemm_kernel(const float* __restrict__ A, const float* __restrict__ Bm,
            const float* __restrict__ bias, float* __restrict__ C,
            int M, int N, int K, int lda, int ldb, int ldc, int relu) {
    __shared__ float As[16][128];
    __shared__ float Bs[16][128];
    int tid = threadIdx.x;
    int tx = tid & 15, ty = tid >> 4;
    int row0 = blockIdx.y * 128, col0 = blockIdx.x * 128;
    float acc[8][8];
#pragma unroll
    for (int i = 0; i < 8; i++)
#pragma unroll
        for (int j = 0; j < 8; j++) acc[i][j] = 0.f;

    int aRow = tid >> 2, aCol = (tid & 3) * 4;   // A: 128x16, 2 f4/thread
    int bRow = tid >> 5, bCol = (tid & 31) * 4;  // B: 16x128, 2 f4/thread

    for (int kb = 0; kb < K; kb += 16) {
#pragma unroll
        for (int r = 0; r < 128; r += 64) {
            int gm = row0 + aRow + r;
            float4 v = make_float4(0.f, 0.f, 0.f, 0.f);
            if (gm < M) v = *(const float4*)(A + (size_t)gm * lda + kb + aCol);
            As[aCol + 0][aRow + r] = v.x;
            As[aCol + 1][aRow + r] = v.y;
            As[aCol + 2][aRow + r] = v.z;
            As[aCol + 3][aRow + r] = v.w;
        }
#pragma unroll
        for (int r = 0; r < 16; r += 8) {
            float4 v = *(const float4*)(Bm + (size_t)(kb + bRow + r) * ldb + col0 + bCol);
            *(float4*)&Bs[bRow + r][bCol] = v;
        }
        __syncthreads();
#pragma unroll
        for (int k = 0; k < 16; k++) {
            float a[8], b[8];
            *(float4*)(a)     = *(float4*)&As[k][ty*8];
            *(float4*)(a + 4) = *(float4*)&As[k][ty*8 + 4];
            *(float4*)(b)     = *(float4*)&Bs[k][tx*8];
            *(float4*)(b + 4) = *(float4*)&Bs[k][tx*8 + 4];
#pragma unroll
            for (int i = 0; i < 8; i++)
#pragma unroll
                for (int j = 0; j < 8; j++) acc[i][j] = fmaf(a[i], b[j], acc[i][j]);
        }
        __syncthreads();
    }
#pragma unroll
    for (int i = 0; i < 8; i++) {
        int gm = row0 + ty*8 + i;
        if (gm >= M) continue;
#pragma unroll
        for (int j4 = 0; j4 < 8; j4 += 4) {
            int gc = col0 + tx*8 + j4;
            float4 v;
            v.x = acc[i][j4+0]; v.y = acc[i][j4+1]; v.z = acc[i][j4+2]; v.w = acc[i][j4+3];
            if (bias) {
                v.x += bias[gc+0]; v.y += bias[gc+1]; v.z += bias[gc+2]; v.w += bias[gc+3];
            }
            if (relu) {
                v.x = fmaxf(v.x, 0.f); v.y = fmaxf(v.y, 0.f);
                v.z = fmaxf(v.z, 0.f); v.w = fmaxf(v.w, 0.f);
            }
            *(float4*)(C + (size_t)gm * ldc + gc) = v;
        }
    }
}

// ---------------------------------------------------------------------------
// Encoder LSTM step: all 4 LSTMs in one launch.
// grid (16, 4): x = unit tile (32 units -> 128 gate cols), y = lstm id.
// g = Xw[t'] + h @ Whh ; gates ; writes h (ping-pong), c, enc_out.
// ---------------------------------------------------------------------------
__global__ void __launch_bounds__(256)
enc_step_kernel(const float* __restrict__ Whh_f, const float* __restrict__ Whh_b, int t) {
    __shared__ float As[16][64];
    __shared__ float Bs[16][128];
    __shared__ float gsm[64][128];
    int l = blockIdx.y;
    int j0 = blockIdx.x * 32;
    const float* Whh = (l & 1) ? Whh_b : Whh_f;
    const float* h = d_hbuf[t & 1][l];
    int tid = threadIdx.x;
    int tx = tid & 15, ty = tid >> 4;
    float acc[4][8];
#pragma unroll
    for (int i = 0; i < 4; i++)
#pragma unroll
        for (int j = 0; j < 8; j++) acc[i][j] = 0.f;

    int aRow = tid >> 2, aCol = (tid & 3) * 4;    // 64x16 tile, 1 f4/thread
    int bRow = tid >> 5, bCol = (tid & 31) * 4;   // 16x128, 2 f4/thread (gate-remapped)

    for (int kb = 0; kb < NH; kb += 16) {
        {
            float4 v = *(const float4*)(h + aRow * NH + kb + aCol);
            As[aCol+0][aRow] = v.x; As[aCol+1][aRow] = v.y;
            As[aCol+2][aRow] = v.z; As[aCol+3][aRow] = v.w;
        }
#pragma unroll
        for (int r = 0; r < 16; r += 8) {
            int gcol = ((bCol >> 5) * NH) + j0 + (bCol & 31);
            float4 v = *(const float4*)(Whh + (size_t)(kb + bRow + r) * H4 + gcol);
            *(float4*)&Bs[bRow + r][bCol] = v;
        }
        __syncthreads();
#pragma unroll
        for (int k = 0; k < 16; k++) {
            float a[4], b[8];
            *(float4*)a       = *(float4*)&As[k][ty*4];
            *(float4*)(b)     = *(float4*)&Bs[k][tx*8];
            *(float4*)(b + 4) = *(float4*)&Bs[k][tx*8 + 4];
#pragma unroll
            for (int i = 0; i < 4; i++)
#pragma unroll
                for (int j = 0; j < 8; j++) acc[i][j] = fmaf(a[i], b[j], acc[i][j]);
        }
        __syncthreads();
    }
#pragma unroll
    for (int i = 0; i < 4; i++) {
        *(float4*)&gsm[ty*4 + i][tx*8]     = *(float4*)&acc[i][0];
        *(float4*)&gsm[ty*4 + i][tx*8 + 4] = *(float4*)&acc[i][4];
    }
    __syncthreads();

    int tX = (l & 1) ? (NS - 1 - t) : t;
    const float* xw = d_Xw[l] + (size_t)(tX * NB) * H4;
    float* hn_buf = d_hbuf[(t + 1) & 1][l];
    float* c_buf = d_cbuf[l];
    float* eo = (l < 2) ? d_enc[0] : d_enc[1];
    int half = (l & 1) * NH;

    for (int p = tid; p < 2048; p += 256) {
        int m = p >> 5, jj = p & 31;
        int j = j0 + jj;
        const float* xr = xw + (size_t)m * H4;
        float gi = gsm[m][jj]      + xr[j];
        float gf = gsm[m][32 + jj] + xr[NH + j];
        float gg = gsm[m][64 + jj] + xr[2*NH + j];
        float go = gsm[m][96 + jj] + xr[3*NH + j];
        float cp = c_buf[m*NH + j];
        float cn = sigf(gf) * cp + sigf(gi) * tanhf(gg);
        float hv = sigf(go) * tanhf(cn);
        c_buf[m*NH + j] = cn;
        hn_buf[m*NH + j] = hv;
        eo[((size_t)m * NS + tX) * H2 + half + j] = hv;
    }
}

// ---------------------------------------------------------------------------
// Fused attention for one decoder step: scores -> softmax -> weighted sum.
// grid (64, 2): x = batch, y = encoder (0 src, 1 rat). Writes A/Ar at step t.
// ---------------------------------------------------------------------------
__global__ void __launch_bounds__(256)
attend_kernel(const float* __restrict__ att_W2, const float* __restrict__ att_b2, int t) {
    __shared__ float qs[H3];
    __shared__ float w2s[H3];
    __shared__ float logits[NS];
    __shared__ float red[8];
    __shared__ float invsum_s;
    int b = blockIdx.x, e = blockIdx.y;
    int tid = threadIdx.x;
    const float* P   = d_P[e];
    const float* enc = d_enc[e];
    float* outA = d_Abuf[e] + (size_t)(t * NB + b) * H2;

    for (int j = tid; j < H3; j += 256) {
        qs[j]  = d_q[b * H3 + j];
        w2s[j] = att_W2[j];
    }
    __syncthreads();

    float b2 = att_b2[0];
    for (int s = 0; s < NS; s++) {
        const float* Prow = P + (size_t)(b * NS + s) * H3;
        float part = 0.f;
        for (int j = tid; j < H3; j += 256) {
            float v = Prow[j] + qs[j];
            v = fmaxf(v, 0.f);
            part += v * w2s[j];
        }
#pragma unroll
        for (int off = 16; off; off >>= 1) part += __shfl_down_sync(0xffffffffu, part, off);
        if ((tid & 31) == 0) red[tid >> 5] = part;
        __syncthreads();
        if (tid == 0) {
            float sum = 0.f;
#pragma unroll
            for (int w = 0; w < 8; w++) sum += red[w];
            logits[s] = sum + b2;
        }
        __syncthreads();
    }
    if (tid == 0) {
        float mx = -1e30f;
        for (int s = 0; s < NS; s++) mx = fmaxf(mx, logits[s]);
        float sm = 0.f;
        for (int s = 0; s < NS; s++) { logits[s] = expf(logits[s] - mx); sm += logits[s]; }
        invsum_s = 1.f / sm;
    }
    __syncthreads();
    float inv = invsum_s;
    for (int ch = tid; ch < H2; ch += 256) {
        float a = 0.f;
        const float* er = enc + (size_t)(b * NS) * H2 + ch;
        for (int s = 0; s < NS; s++) a += logits[s] * er[(size_t)s * H2];
        outA[ch] = a * inv;
    }
}

// ---------------------------------------------------------------------------
// Decoder LSTM step. grid (32): unit tile of 16 units (64 gate cols).
// g = tgtW[t] + [A, Ar] @ Wih[512:] + h @ Whh ; gates ; h ping-pong, c in place.
// ---------------------------------------------------------------------------
__global__ void __launch_bounds__(256)
dec_step_kernel(const float* __restrict__ dec_Wih, const float* __restrict__ dec_Whh, int t) {
    __shared__ float As[16][64];
    __shared__ float Bs[16][64];
    __shared__ float gsm[64][64];
    int j0 = blockIdx.x * 16;
    int tid = threadIdx.x;
    int tx = tid & 15, ty = tid >> 4;
    float acc[4][4];
#pragma unroll
    for (int i = 0; i < 4; i++)
#pragma unroll
        for (int j = 0; j < 4; j++) acc[i][j] = 0.f;

    const float* hdec  = d_hdec[t & 1];
    const float* Abuf  = d_Abuf[0] + (size_t)(t * NB) * H2;
    const float* Arbuf = d_Abuf[1] + (size_t)(t * NB) * H2;

    int aRow = tid >> 2, aCol = (tid & 3) * 4;   // 64x16, 1 f4/thread
    int bRow = tid >> 4, bCol = (tid & 15) * 4;  // 16x64, 1 f4/thread

    for (int kb = 0; kb < 2560; kb += 16) {
        const float* asrc; int stride, koff;
        if (kb < 1024)      { asrc = Abuf;  stride = H2; koff = kb; }
        else if (kb < 2048) { asrc = Arbuf; stride = H2; koff = kb - 1024; }
        else                { asrc = hdec;  stride = NH; koff = kb - 2048; }
        {
            float4 v = *(const float4*)(asrc + (size_t)aRow * stride + koff + aCol);
            As[aCol+0][aRow] = v.x; As[aCol+1][aRow] = v.y;
            As[aCol+2][aRow] = v.z; As[aCol+3][aRow] = v.w;
        }
        {
            int k = kb + bRow;
            const float* Brow = (k < 2048) ? (dec_Wih + (size_t)(NE + k) * H4)
                                           : (dec_Whh + (size_t)(k - 2048) * H4);
            int gcol = (bCol >> 4) * NH + j0 + (bCol & 15);
            *(float4*)&Bs[bRow][bCol] = *(const float4*)(Brow + gcol);
        }
        __syncthreads();
#pragma unroll
        for (int k = 0; k < 16; k++) {
            float a[4], b[4];
            *(float4*)a = *(float4*)&As[k][ty*4];
            *(float4*)b = *(float4*)&Bs[k][tx*4];
#pragma unroll
            for (int i = 0; i < 4; i++)
#pragma unroll
                for (int j = 0; j < 4; j++) acc[i][j] = fmaf(a[i], b[j], acc[i][j]);
        }
        __syncthreads();
    }
#pragma unroll
    for (int i = 0; i < 4; i++)
        *(float4*)&gsm[ty*4 + i][tx*4] = *(float4*)&acc[i][0];
    __syncthreads();

    const float* tw = d_tgtW + (size_t)(t * NB) * H4;
    float* hn = d_hdec[(t + 1) & 1];
    for (int p = tid; p < 1024; p += 256) {
        int m = p >> 4, jj = p & 15;
        int j = j0 + jj;
        const float* tr = tw + (size_t)m * H4;
        float gi = gsm[m][jj]      + tr[j];
        float gf = gsm[m][16 + jj] + tr[NH + j];
        float gg = gsm[m][32 + jj] + tr[2*NH + j];
        float go = gsm[m][48 + jj] + tr[3*NH + j];
        float cp = d_cdec[m*NH + j];
        float cn = sigf(gf) * cp + sigf(gi) * tanhf(gg);
        float hv = sigf(go) * tanhf(cn);
        d_cdec[m*NH + j] = cn;
        hn[m*NH + j] = hv;
        d_Dbuf[((size_t)t * NB + m) * NH + j] = hv;
    }
}

// ---------------------------------------------------------------------------
// Assemble classifier input ci[r = b*T+t] = [tgt_e, A, Ar, g, D] (zeros past STEPS)
// ---------------------------------------------------------------------------
__global__ void assemble_kernel(const float* __restrict__ graph_embs) {
    int r = blockIdx.x;
    int b = r >> 6, t = r & 63;
    float* row = d_ci + (size_t)r * CIW;
    bool live = (t < NSTEPS);
    for (int c = threadIdx.x; c < CIW; c += 256) {
        float v;
        if (c < 512)       v = d_tgt_e[((size_t)t * NB + b) * NE + c];
        else if (c < 1536) v = live ? d_Abuf[0][((size_t)t * NB + b) * H2 + (c - 512)]  : 0.f;
        else if (c < 2560) v = live ? d_Abuf[1][((size_t)t * NB + b) * H2 + (c - 1536)] : 0.f;
        else if (c < 2816) v = graph_embs[b * NG + (c - 2560)];
        else               v = live ? d_Dbuf[((size_t)t * NB + b) * NH + (c - 2816)]    : 0.f;
        row[c] = v;
    }
}

// ---------------------------------------------------------------------------
// Host launch
// ---------------------------------------------------------------------------
static float* symaddr(const void* s) {
    void* p = nullptr;
    cudaGetSymbolAddress(&p, s);
    return (float*)p;
}

static void gemm(const float* A, const float* B, const float* bias, float* C,
                 int M, int N, int K, int lda, int ldb, int ldc, int relu) {
    dim3 g(N / 128, (M + 127) / 128);
    gemm_kernel<<<g, 256>>>(A, B, bias, C, M, N, K, lda, ldb, ldc, relu);
}

extern "C" void kernel_launch(void* const* d_in, const int* in_sizes, int n_in,
                              void* d_out, int out_size) {
    const int*   source_data = (const int*)d_in[0];
    const int*   target_data = (const int*)d_in[1];
    const int*   rationales  = (const int*)d_in[2];
    const float* graph_embs  = (const float*)d_in[3];
    const float* src_emb     = (const float*)d_in[4];
    const float* tgt_emb     = (const float*)d_in[5];
    const float* enc_Wih_f   = (const float*)d_in[6];
    const float* enc_Whh_f   = (const float*)d_in[7];
    const float* enc_b_f     = (const float*)d_in[8];
    const float* enc_Wih_b   = (const float*)d_in[9];
    const float* enc_Whh_b   = (const float*)d_in[10];
    const float* enc_b_b     = (const float*)d_in[11];
    const float* dec_Wih     = (const float*)d_in[12];
    const float* dec_Whh     = (const float*)d_in[13];
    const float* dec_b       = (const float*)d_in[14];
    const float* att_W1      = (const float*)d_in[15];
    const float* att_b1      = (const float*)d_in[16];
    const float* att_W2      = (const float*)d_in[17];
    const float* att_b2      = (const float*)d_in[18];
    const float* cls_Wg      = (const float*)d_in[19];
    const float* cls_bg      = (const float*)d_in[20];
    const float* cls_W2      = (const float*)d_in[21];
    const float* cls_b2      = (const float*)d_in[22];
    float* out = (float*)d_out;

    float* p_src_e = symaddr(d_src_e);
    float* p_rat_e = symaddr(d_rat_e);
    float* p_tgt_e = symaddr(d_tgt_e);
    float* p_Xw    = symaddr(d_Xw);
    float* p_enc   = symaddr(d_enc);
    float* p_P     = symaddr(d_P);
    float* p_q     = symaddr(d_q);
    float* p_hdec  = symaddr(d_hdec);
    float* p_tgtW  = symaddr(d_tgtW);
    float* p_ci    = symaddr(d_ci);
    float* p_hid   = symaddr(d_hid);

    const size_t XW  = (size_t)NS * NB * H4;
    const size_t ENC = (size_t)NB * NS * H2;
    const size_t PP  = (size_t)NB * NS * H3;

    zero_state_kernel<<<1024, 256>>>();
    gather_kernel<<<dim3(4096, 3), 256>>>(source_data, target_data, rationales,
                                          src_emb, tgt_emb);

    // x @ Wih + b, hoisted for all 4 encoder LSTMs
    gemm(p_src_e, enc_Wih_f, enc_b_f, p_Xw + 0*XW, 4096, H4, NE, NE, H4, H4, 0);
    gemm(p_src_e, enc_Wih_b, enc_b_b, p_Xw + 1*XW, 4096, H4, NE, NE, H4, H4, 0);
    gemm(p_rat_e, enc_Wih_f, enc_b_f, p_Xw + 2*XW, 4096, H4, NE, NE, H4, H4, 0);
    gemm(p_rat_e, enc_Wih_b, enc_b_b, p_Xw + 3*XW, 4096, H4, NE, NE, H4, H4, 0);

    // tgt_e @ dec_Wih[:E] + dec_b, hoisted for all 32 decoder steps
    gemm(p_tgt_e, dec_Wih, dec_b, p_tgtW, NSTEPS * NB, H4, NE, NE, H4, H4, 0);

    // encoder recurrence: 64 steps, 4 LSTMs per launch
    for (int t = 0; t < NS; t++)
        enc_step_kernel<<<dim3(16, 4), 256>>>(enc_Whh_f, enc_Whh_b, t);

    init_dec_state_kernel<<<128, 256>>>();

    // attention pre-projection: enc_out @ W1[:2H] + b1
    gemm(p_enc + 0*ENC, att_W1, att_b1, p_P + 0*PP, 4096, H3, H2, H2, H3, H3, 0);
    gemm(p_enc + 1*ENC, att_W1, att_b1, p_P + 1*PP, 4096, H3, H2, H2, H3, H3, 0);

    // decoder recurrence
    for (int t = 0; t < NSTEPS; t++) {
        // q = h @ W1[2H:]; shared by both attends
        gemm(p_hdec + (size_t)(t & 1) * NB * NH, att_W1 + (size_t)H2 * H3, nullptr,
             p_q, NB, H3, NH, NH, H3, H3, 0);
        attend_kernel<<<dim3(NB, 2), 256>>>(att_W2, att_b2, t);
        dec_step_kernel<<<32, 256>>>(dec_Wih, dec_Whh, t);
    }

    // classifier
    assemble_kernel<<<4096, 256>>>(graph_embs);
    gemm(p_ci,  cls_Wg, cls_bg, p_hid, 4096, H2, CIW, CIW, H2, H2, 1);
    gemm(p_hid, cls_W2, cls_b2, out,   4096, NV,  H2,  H2, NV, NV, 0);
}

// round 2
// speedup vs baseline: 1.8445x; 1.8445x over previous
#include <cuda_runtime.h>
#include <math.h>

// ---------------------------------------------------------------------------
// Problem constants: B=64, S=64, T=64, STEPS=32, E=512, H=512, G=256, V=32000
// ---------------------------------------------------------------------------
#define NB   64
#define NS   64
#define NT   64
#define NSTEPS 32
#define NE   512
#define NH   512
#define NG   256
#define NV   32000
#define H4   2048
#define H2   1024
#define H3   1536
#define CIW  3328   // E + 2H + 2H + G + H

#define GRID_PERS 128   // persistent-kernel grid (<=148 SMs -> co-resident)

// ---------------------------------------------------------------------------
// Scratch (device globals; no allocations allowed)
// ---------------------------------------------------------------------------
__device__ float d_src_e[NS*NB*NE];        // time-major [s][b][e]
__device__ float d_rat_e[NS*NB*NE];
__device__ float d_tgt_e[NT*NB*NE];        // [t][b][e]
__device__ float d_Xw[4][NS*NB*H4];        // x@Wih + b per lstm {srcF,srcB,ratF,ratB}
__device__ float d_hbuf[2][4][NB*NH];      // ping-pong h (encoder)
__device__ float d_enc[2][NB*NS*H2];       // [b][s][2H]; 0=src 1=rat
__device__ float d_P[2][NB*NS*H3];         // enc_out @ W1[:2H] + b1
__device__ float d_q[NB*H3];               // h @ W1[2H:]
__device__ float d_Abuf[2][NSTEPS*NB*H2];  // attention outputs A, Ar
__device__ float d_Dbuf[NSTEPS*NB*NH];     // decoder h per step
__device__ float d_tgtW[NSTEPS*NB*H4];     // tgt_e @ dec_Wih[:E] + dec_b
__device__ float d_hdec[2][NB*NH];
__device__ float d_cfin[NB*NH];            // encoder (src,fwd) final c
__device__ float d_gpart[4*NB*H4];         // decoder gemm K-split partials
__device__ float d_ci[(size_t)NB*NT*CIW];
__device__ float d_hid[(size_t)NB*NT*H2];
__device__ unsigned int g_bar = 0;

__device__ __forceinline__ float sigf(float x) { return 1.f / (1.f + expf(-x)); }

// Software grid barrier. All GRID_PERS blocks must be co-resident.
__device__ __forceinline__ void grid_bar() {
    __syncthreads();
    if (threadIdx.x == 0) {
        __threadfence();                       // release
        unsigned int t = atomicAdd(&g_bar, 1u);
        unsigned int target = t - (t & (GRID_PERS - 1u)) + GRID_PERS;
        unsigned int v;
        do {
            asm volatile("ld.acquire.gpu.global.u32 %0, [%1];"
                         : "=r"(v) : "l"(&g_bar) : "memory");
        } while (v < target);
    }
    __syncthreads();
}

// ---------------------------------------------------------------------------
// Zero / gather
// ---------------------------------------------------------------------------
__global__ void zero_state_kernel() {
    int i = blockIdx.x * 256 + threadIdx.x;
    if (i < 2*4*NB*NH) ((float*)d_hbuf)[i] = 0.f;
}

__global__ void gather_kernel(const int* __restrict__ src_ids,
                              const int* __restrict__ tgt_ids,
                              const int* __restrict__ rat_ids,
                              const float* __restrict__ src_emb,
                              const float* __restrict__ tgt_emb) {
    int tok = blockIdx.x;          // s*64 + b
    int set = blockIdx.y;          // 0 src, 1 rat, 2 tgt
    int s = tok >> 6, b = tok & 63;
    int id;
    const float* emb;
    float* out;
    if (set == 0)      { id = src_ids[b*NS + s]; emb = src_emb; out = d_src_e; }
    else if (set == 1) { id = rat_ids[b*NS + s]; emb = src_emb; out = d_rat_e; }
    else               { id = tgt_ids[b*NT + s]; emb = tgt_emb; out = d_tgt_e; }
    const float* row = emb + (size_t)id * NE;
    float* dst = out + (size_t)tok * NE;
    for (int e = threadIdx.x; e < NE; e += 256) dst[e] = row[e];
}

// ---------------------------------------------------------------------------
// Generic fp32 GEMM: C[M,N] = A[M,K] @ B[K,N] (+bias) (+relu)  (unchanged)
// ---------------------------------------------------------------------------
__global__ void __launch_bounds__(256)
gemm_kernel(const float* __restrict__ A, const float* __restrict__ Bm,
            const float* __restrict__ bias, float* __restrict__ C,
            int M, int N, int K, int lda, int ldb, int ldc, int relu) {
    __shared__ float As[16][128];
    __shared__ float Bs[16][128];
    int tid = threadIdx.x;
    int tx = tid & 15, ty = tid >> 4;
    int row0 = blockIdx.y * 128, col0 = blockIdx.x * 128;
    float acc[8][8];
#pragma unroll
    for (int i = 0; i < 8; i++)
#pragma unroll
        for (int j = 0; j < 8; j++) acc[i][j] = 0.f;

    int aRow = tid >> 2, aCol = (tid & 3) * 4;
    int bRow = tid >> 5, bCol = (tid & 31) * 4;

    for (int kb = 0; kb < K; kb += 16) {
#pragma unroll
        for (int r = 0; r < 128; r += 64) {
            int gm = row0 + aRow + r;
            float4 v = make_float4(0.f, 0.f, 0.f, 0.f);
            if (gm < M) v = *(const float4*)(A + (size_t)gm * lda + kb + aCol);
            As[aCol + 0][aRow + r] = v.x;
            As[aCol + 1][aRow + r] = v.y;
            As[aCol + 2][aRow + r] = v.z;
            As[aCol + 3][aRow + r] = v.w;
        }
#pragma unroll
        for (int r = 0; r < 16; r += 8) {
            float4 v = *(const float4*)(Bm + (size_t)(kb + bRow + r) * ldb + col0 + bCol);
            *(float4*)&Bs[bRow + r][bCol] = v;
        }
        __syncthreads();
#pragma unroll
        for (int k = 0; k < 16; k++) {
            float a[8], b[8];
            *(float4*)(a)     = *(float4*)&As[k][ty*8];
            *(float4*)(a + 4) = *(float4*)&As[k][ty*8 + 4];
            *(float4*)(b)     = *(float4*)&Bs[k][tx*8];
            *(float4*)(b + 4) = *(float4*)&Bs[k][tx*8 + 4];
#pragma unroll
            for (int i = 0; i < 8; i++)
#pragma unroll
                for (int j = 0; j < 8; j++) acc[i][j] = fmaf(a[i], b[j], acc[i][j]);
        }
        __syncthreads();
    }
#pragma unroll
    for (int i = 0; i < 8; i++) {
        int gm = row0 + ty*8 + i;
        if (gm >= M) continue;
#pragma unroll
        for (int j4 = 0; j4 < 8; j4 += 4) {
            int gc = col0 + tx*8 + j4;
            float4 v;
            v.x = acc[i][j4+0]; v.y = acc[i][j4+1]; v.z = acc[i][j4+2]; v.w = acc[i][j4+3];
            if (bias) {
                v.x += bias[gc+0]; v.y += bias[gc+1]; v.z += bias[gc+2]; v.w += bias[gc+3];
            }
            if (relu) {
                v.x = fmaxf(v.x, 0.f); v.y = fmaxf(v.y, 0.f);
                v.z = fmaxf(v.z, 0.f); v.w = fmaxf(v.w, 0.f);
            }
            *(float4*)(C + (size_t)gm * ldc + gc) = v;
        }
    }
}

// ---------------------------------------------------------------------------
// Persistent encoder: all 64 steps, 4 LSTMs, one kernel.
// 128 blocks = 4 lstms x 32 unit-tiles (16 units -> 64 gate cols each).
// c lives in smem for the whole recurrence; h ping-pongs through global
// (cross-block reads via __ldcg). One grid barrier per step.
// ---------------------------------------------------------------------------
__global__ void __launch_bounds__(256)
enc_persistent_kernel(const float* __restrict__ Whh_f,
                      const float* __restrict__ Whh_b) {
    __shared__ float As[16][64];
    __shared__ float Bs[16][68];
    __shared__ float gsm[64][68];
    __shared__ float cs[64][16];
    int blk = blockIdx.x;
    int l = blk >> 5;                 // lstm id {srcF,srcB,ratF,ratB}
    int j0 = (blk & 31) * 16;         // unit-tile base
    const float* Whh = (l & 1) ? Whh_b : Whh_f;
    int tid = threadIdx.x;
    int tx = tid & 15, ty = tid >> 4;

    for (int p = tid; p < 1024; p += 256) ((float*)cs)[p] = 0.f;

    int aRow = tid >> 2, aCol = (tid & 3) * 4;
    int bRow = tid >> 4, bCol = tx * 4;
    const float* Bbase = Whh + (bCol >> 4) * NH + j0 + (bCol & 15);

    float* eo = (l < 2) ? d_enc[0] : d_enc[1];
    int half = (l & 1) * NH;

    for (int t = 0; t < NS; t++) {
        const float* h = d_hbuf[t & 1][l];
        float acc[4][4];
#pragma unroll
        for (int i = 0; i < 4; i++)
#pragma unroll
            for (int j = 0; j < 4; j++) acc[i][j] = 0.f;

        for (int kb = 0; kb < NH; kb += 16) {
            float4 va = __ldcg((const float4*)(h + aRow * NH + kb + aCol));
            As[aCol+0][aRow] = va.x; As[aCol+1][aRow] = va.y;
            As[aCol+2][aRow] = va.z; As[aCol+3][aRow] = va.w;
            float4 vb = *(const float4*)(Bbase + (size_t)(kb + bRow) * H4);
            *(float4*)&Bs[bRow][bCol] = vb;
            __syncthreads();
#pragma unroll
            for (int k = 0; k < 16; k++) {
                float a[4], b[4];
                *(float4*)a = *(float4*)&As[k][ty*4];
                *(float4*)b = *(float4*)&Bs[k][tx*4];
#pragma unroll
                for (int i = 0; i < 4; i++)
#pragma unroll
                    for (int j = 0; j < 4; j++) acc[i][j] = fmaf(a[i], b[j], acc[i][j]);
            }
            __syncthreads();
        }
#pragma unroll
        for (int i = 0; i < 4; i++)
            *(float4*)&gsm[ty*4 + i][tx*4] = *(float4*)&acc[i][0];
        __syncthreads();

        int tX = (l & 1) ? (NS - 1 - t) : t;
        const float* xw = d_Xw[l] + (size_t)(tX * NB) * H4;
        float* hn = d_hbuf[(t + 1) & 1][l];
        for (int p = tid; p < 1024; p += 256) {
            int m = p >> 4, jj = p & 15;
            int j = j0 + jj;
            const float* xr = xw + (size_t)m * H4;
            float gi = gsm[m][jj]      + xr[j];
            float gf = gsm[m][16 + jj] + xr[NH + j];
            float gg = gsm[m][32 + jj] + xr[2*NH + j];
            float go = gsm[m][48 + jj] + xr[3*NH + j];
            float cp = cs[m][jj];
            float cn = sigf(gf) * cp + sigf(gi) * tanhf(gg);
            float hv = sigf(go) * tanhf(cn);
            cs[m][jj] = cn;
            hn[m*NH + j] = hv;
            eo[((size_t)m * NS + tX) * H2 + half + j] = hv;
        }
        grid_bar();
    }
    // dump (src,fwd) final c for decoder init
    if (l == 0) {
        for (int p = tid; p < 1024; p += 256) {
            int m = p >> 4, jj = p & 15;
            d_cfin[m*NH + j0 + jj] = cs[m][jj];
        }
    }
}

// ---------------------------------------------------------------------------
// Persistent decoder: all 32 steps, one kernel, 4 phases/step.
//  P1: q = h @ W1[2H:]           (blocks 0..95, 16-col tiles)
//  P2: attend (128 blocks = 64 batches x 2 encoders)
//  P3: dec gemm, K=2560 split 4 ways -> d_gpart (128 blocks = 32 col x 4 ksplit)
//  P4: gates: 1 thread per (batch,unit); c in a register across steps
// ---------------------------------------------------------------------------
__global__ void __launch_bounds__(256)
dec_persistent_kernel(const float* __restrict__ dec_Wih,
                      const float* __restrict__ dec_Whh,
                      const float* __restrict__ att_W1,
                      const float* __restrict__ att_W2,
                      const float* __restrict__ att_b2) {
    __shared__ float As[16][64];
    __shared__ float Bs[16][68];
    __shared__ float Bq[16][17];
    __shared__ float qs[H3];
    __shared__ float w2s[H3];
    __shared__ float logits[NS];
    __shared__ float wts[NS];
    __shared__ float sred[2];

    int blk = blockIdx.x, tid = threadIdx.x;
    int tx = tid & 15, ty = tid >> 4;
    int aRow = tid >> 2, aCol = (tid & 3) * 4;

    // phase-4 ownership: one thread per (batch m, unit j), fixed across steps
    int p = blk * 256 + tid;           // 0..32767
    int pm = p >> 9, pj = p & 511;
    float c_reg = d_cfin[pm * NH + pj];

    for (int t = 0; t < NSTEPS; t++) {
        const float* h = (t == 0) ? d_hbuf[0][0] : d_hdec[t & 1];

        // ---- Phase 1: q[64,1536] = h[64,512] @ W1[1024:1536, :]
        if (blk < 96) {
            int c0 = blk * 16;
            float acc[4] = {0.f, 0.f, 0.f, 0.f};
            for (int kb = 0; kb < NH; kb += 16) {
                float4 va = __ldcg((const float4*)(h + aRow * NH + kb + aCol));
                As[aCol+0][aRow] = va.x; As[aCol+1][aRow] = va.y;
                As[aCol+2][aRow] = va.z; As[aCol+3][aRow] = va.w;
                Bq[tid >> 4][tid & 15] =
                    att_W1[(size_t)(H2 + kb + (tid >> 4)) * H3 + c0 + (tid & 15)];
                __syncthreads();
#pragma unroll
                for (int k = 0; k < 16; k++) {
                    float b = Bq[k][tx];
#pragma unroll
                    for (int i = 0; i < 4; i++)
                        acc[i] = fmaf(As[k][ty*4 + i], b, acc[i]);
                }
                __syncthreads();
            }
#pragma unroll
            for (int i = 0; i < 4; i++)
                d_q[(ty*4 + i) * H3 + c0 + tx] = acc[i];
        }
        grid_bar();

        // ---- Phase 2: attention (both encoders)
        {
            int b = blk & 63, e = blk >> 6;
            const float* P   = d_P[e] + (size_t)(b * NS) * H3;
            const float* enc = d_enc[e] + (size_t)(b * NS) * H2;
            for (int j2 = tid; j2 < H3; j2 += 256) {
                qs[j2]  = __ldcg(&d_q[b * H3 + j2]);
                w2s[j2] = att_W2[j2];
            }
            __syncthreads();
            int w = tid >> 5, lane = tid & 31;
            float b2v = att_b2[0];
#pragma unroll
            for (int si = 0; si < 8; si++) {
                int s = w * 8 + si;
                const float* Pr = P + (size_t)s * H3;
                float part = 0.f;
                for (int j2 = lane; j2 < H3; j2 += 32)
                    part += fmaxf(Pr[j2] + qs[j2], 0.f) * w2s[j2];
#pragma unroll
                for (int off = 16; off; off >>= 1)
                    part += __shfl_down_sync(0xffffffffu, part, off);
                if (lane == 0) logits[s] = part + b2v;
            }
            __syncthreads();
            if (tid == 0) {
                float mx = -1e30f;
                for (int s = 0; s < NS; s++) mx = fmaxf(mx, logits[s]);
                sred[0] = mx;
            }
            __syncthreads();
            if (tid < NS) wts[tid] = expf(logits[tid] - sred[0]);
            __syncthreads();
            if (tid == 0) {
                float sm = 0.f;
                for (int s = 0; s < NS; s++) sm += wts[s];
                sred[1] = 1.f / sm;
            }
            __syncthreads();
            float inv = sred[1];
            float* outA = d_Abuf[e] + (size_t)(t * NB + b) * H2;
            for (int ch = tid; ch < H2; ch += 256) {
                float a = 0.f;
                for (int s = 0; s < NS; s++)
                    a += wts[s] * enc[(size_t)s * H2 + ch];
                outA[ch] = a * inv;
            }
        }
        grid_bar();

        // ---- Phase 3: dec gemm partials: [A,Ar,h] @ [Wih[512:],Whh], K split x4
        {
            int ks = blk >> 5, ct = blk & 31;
            int c0 = ct * 64;
            const float* Ab  = d_Abuf[0] + (size_t)(t * NB) * H2;
            const float* Arb = d_Abuf[1] + (size_t)(t * NB) * H2;
            float acc[4][4];
#pragma unroll
            for (int i = 0; i < 4; i++)
#pragma unroll
                for (int j = 0; j < 4; j++) acc[i][j] = 0.f;

            int k0 = ks * 640;
            for (int kb = k0; kb < k0 + 640; kb += 16) {
                const float* asrc; int stride, koff;
                if (kb < 1024)      { asrc = Ab;  stride = H2; koff = kb; }
                else if (kb < 2048) { asrc = Arb; stride = H2; koff = kb - 1024; }
                else                { asrc = h;   stride = NH; koff = kb - 2048; }
                float4 va = __ldcg((const float4*)(asrc + (size_t)aRow * stride + koff + aCol));
                As[aCol+0][aRow] = va.x; As[aCol+1][aRow] = va.y;
                As[aCol+2][aRow] = va.z; As[aCol+3][aRow] = va.w;
                int kk = kb + (tid >> 4);
                const float* Brow = (kk < 2048) ? (dec_Wih + (size_t)(NE + kk) * H4)
                                                : (dec_Whh + (size_t)(kk - 2048) * H4);
                *(float4*)&Bs[tid >> 4][tx * 4] = *(const float4*)(Brow + c0 + tx * 4);
                __syncthreads();
#pragma unroll
                for (int k = 0; k < 16; k++) {
                    float a[4], b[4];
                    *(float4*)a = *(float4*)&As[k][ty*4];
                    *(float4*)b = *(float4*)&Bs[k][tx*4];
#pragma unroll
                    for (int i = 0; i < 4; i++)
#pragma unroll
                        for (int j = 0; j < 4; j++) acc[i][j] = fmaf(a[i], b[j], acc[i][j]);
                }
                __syncthreads();
            }
            float* gp = d_gpart + (size_t)(ks * NB) * H4;
#pragma unroll
            for (int i = 0; i < 4; i++)
                *(float4*)(gp + (size_t)(ty*4 + i) * H4 + c0 + tx*4) = *(float4*)&acc[i][0];
        }
        grid_bar();

        // ---- Phase 4: gates (1 thread per (m,j))
        {
            const float* xr = d_tgtW + (size_t)(t * NB + pm) * H4;
            float g4[4];
#pragma unroll
            for (int g = 0; g < 4; g++) {
                float v = xr[g * NH + pj];
#pragma unroll
                for (int ks = 0; ks < 4; ks++)
                    v += __ldcg(&d_gpart[(size_t)(ks * NB + pm) * H4 + g * NH + pj]);
                g4[g] = v;
            }
            float cn = sigf(g4[1]) * c_reg + sigf(g4[0]) * tanhf(g4[2]);
            float hv = sigf(g4[3]) * tanhf(cn);
            c_reg = cn;
            d_hdec[(t + 1) & 1][pm * NH + pj] = hv;
            d_Dbuf[((size_t)t * NB + pm) * NH + pj] = hv;
        }
        grid_bar();
    }
}

// ---------------------------------------------------------------------------
// Assemble classifier input ci[r=b*T+t] = [tgt_e, A, Ar, g, D] (zeros past STEPS)
// ---------------------------------------------------------------------------
__global__ void assemble_kernel(const float* __restrict__ graph_embs) {
    int r = blockIdx.x;
    int b = r >> 6, t = r & 63;
    float* row = d_ci + (size_t)r * CIW;
    bool live = (t < NSTEPS);
    for (int c = threadIdx.x; c < CIW; c += 256) {
        float v;
        if (c < 512)       v = d_tgt_e[((size_t)t * NB + b) * NE + c];
        else if (c < 1536) v = live ? d_Abuf[0][((size_t)t * NB + b) * H2 + (c - 512)]  : 0.f;
        else if (c < 2560) v = live ? d_Abuf[1][((size_t)t * NB + b) * H2 + (c - 1536)] : 0.f;
        else if (c < 2816) v = graph_embs[b * NG + (c - 2560)];
        else               v = live ? d_Dbuf[((size_t)t * NB + b) * NH + (c - 2816)]    : 0.f;
        row[c] = v;
    }
}

// ---------------------------------------------------------------------------
// Host launch
// ---------------------------------------------------------------------------
static float* symaddr(const void* s) {
    void* p = nullptr;
    cudaGetSymbolAddress(&p, s);
    return (float*)p;
}

static void gemm(const float* A, const float* B, const float* bias, float* C,
                 int M, int N, int K, int lda, int ldb, int ldc, int relu) {
    dim3 g(N / 128, (M + 127) / 128);
    gemm_kernel<<<g, 256>>>(A, B, bias, C, M, N, K, lda, ldb, ldc, relu);
}

extern "C" void kernel_launch(void* const* d_in, const int* in_sizes, int n_in,
                              void* d_out, int out_size) {
    const int*   source_data = (const int*)d_in[0];
    const int*   target_data = (const int*)d_in[1];
    const int*   rationales  = (const int*)d_in[2];
    const float* graph_embs  = (const float*)d_in[3];
    const float* src_emb     = (const float*)d_in[4];
    const float* tgt_emb     = (const float*)d_in[5];
    const float* enc_Wih_f   = (const float*)d_in[6];
    const float* enc_Whh_f   = (const float*)d_in[7];
    const float* enc_b_f     = (const float*)d_in[8];
    const float* enc_Wih_b   = (const float*)d_in[9];
    const float* enc_Whh_b   = (const float*)d_in[10];
    const float* enc_b_b     = (const float*)d_in[11];
    const float* dec_Wih     = (const float*)d_in[12];
    const float* dec_Whh     = (const float*)d_in[13];
    const float* dec_b       = (const float*)d_in[14];
    const float* att_W1      = (const float*)d_in[15];
    const float* att_b1      = (const float*)d_in[16];
    const float* att_W2      = (const float*)d_in[17];
    const float* att_b2      = (const float*)d_in[18];
    const float* cls_Wg      = (const float*)d_in[19];
    const float* cls_bg      = (const float*)d_in[20];
    const float* cls_W2      = (const float*)d_in[21];
    const float* cls_b2      = (const float*)d_in[22];
    float* out = (float*)d_out;

    float* p_src_e = symaddr(d_src_e);
    float* p_rat_e = symaddr(d_rat_e);
    float* p_tgt_e = symaddr(d_tgt_e);
    float* p_Xw    = symaddr(d_Xw);
    float* p_enc   = symaddr(d_enc);
    float* p_P     = symaddr(d_P);
    float* p_tgtW  = symaddr(d_tgtW);
    float* p_ci    = symaddr(d_ci);
    float* p_hid   = symaddr(d_hid);
    void*  p_bar   = nullptr;
    cudaGetSymbolAddress(&p_bar, g_bar);

    const size_t XW  = (size_t)NS * NB * H4;
    const size_t ENC = (size_t)NB * NS * H2;
    const size_t PP  = (size_t)NB * NS * H3;

    cudaMemsetAsync(p_bar, 0, sizeof(unsigned int));
    zero_state_kernel<<<1024, 256>>>();
    gather_kernel<<<dim3(4096, 3), 256>>>(source_data, target_data, rationales,
                                          src_emb, tgt_emb);

    // x @ Wih + b, hoisted for all 4 encoder LSTMs
    gemm(p_src_e, enc_Wih_f, enc_b_f, p_Xw + 0*XW, 4096, H4, NE, NE, H4, H4, 0);
    gemm(p_src_e, enc_Wih_b, enc_b_b, p_Xw + 1*XW, 4096, H4, NE, NE, H4, H4, 0);
    gemm(p_rat_e, enc_Wih_f, enc_b_f, p_Xw + 2*XW, 4096, H4, NE, NE, H4, H4, 0);
    gemm(p_rat_e, enc_Wih_b, enc_b_b, p_Xw + 3*XW, 4096, H4, NE, NE, H4, H4, 0);

    // tgt_e @ dec_Wih[:E] + dec_b, hoisted for all 32 decoder steps
    gemm(p_tgt_e, dec_Wih, dec_b, p_tgtW, NSTEPS * NB, H4, NE, NE, H4, H4, 0);

    // encoder recurrence: one persistent kernel, 64 steps
    enc_persistent_kernel<<<GRID_PERS, 256>>>(enc_Whh_f, enc_Whh_b);

    // attention pre-projection: enc_out @ W1[:2H] + b1
    gemm(p_enc + 0*ENC, att_W1, att_b1, p_P + 0*PP, 4096, H3, H2, H2, H3, H3, 0);
    gemm(p_enc + 1*ENC, att_W1, att_b1, p_P + 1*PP, 4096, H3, H2, H2, H3, H3, 0);

    // decoder recurrence: one persistent kernel, 32 steps
    dec_persistent_kernel<<<GRID_PERS, 256>>>(dec_Wih, dec_Whh,
                                              att_W1, att_W2, att_b2);

    // classifier
    assemble_kernel<<<4096, 256>>>(graph_embs);
    gemm(p_ci,  cls_Wg, cls_bg, p_hid, 4096, H2, CIW, CIW, H2, H2, 1);
    gemm(p_hid, cls_W2, cls_b2, out,   4096, NV,  H2,  H2, NV, NV, 0);
}

// round 5
// speedup vs baseline: 2.5816x; 1.3996x over previous
#include <cuda_runtime.h>
#include <math.h>
#include <stdint.h>

// ---------------------------------------------------------------------------
// Problem constants: B=64, S=64, T=64, STEPS=32, E=512, H=512, G=256, V=32000
// ---------------------------------------------------------------------------
#define NB   64
#define NS   64
#define NT   64
#define NSTEPS 32
#define NE   512
#define NH   512
#define NG   256
#define NV   32000
#define H4   2048
#define H2   1024
#define H3   1536
#define CIW  3328   // E + 2H + 2H + G + H

#define GRID_PERS 128   // persistent-kernel grid (<=148 SMs -> co-resident)

// ---------------------------------------------------------------------------
// Scratch (device globals; no allocations allowed)
// ---------------------------------------------------------------------------
__device__ float d_src_e[NS*NB*NE];        // time-major [s][b][e]
__device__ float d_rat_e[NS*NB*NE];
__device__ float d_tgt_e[NT*NB*NE];        // [t][b][e]
__device__ float d_Xw[4][NS*NB*H4];        // x@Wih + b per lstm {srcF,srcB,ratF,ratB}
__device__ float d_hbuf[2][4][NB*NH];      // ping-pong h (encoder)
__device__ float d_enc[2][NB*NS*H2];       // [b][s][2H]; 0=src 1=rat
__device__ float d_P[2][NB*NS*H3];         // enc_out @ W1[:2H] + b1
__device__ float d_q[NB*H3];               // h @ W1[2H:]
__device__ float d_Abuf[2][NSTEPS*NB*H2];  // attention outputs A, Ar
__device__ float d_Dbuf[NSTEPS*NB*NH];     // decoder h per step
__device__ float d_tgtW[NSTEPS*NB*H4];     // tgt_e @ dec_Wih[:E] + dec_b
__device__ float d_hdec[2][NB*NH];
__device__ float d_cfin[NB*NH];            // encoder (src,fwd) final c
__device__ float d_gpart[4*NB*H4];         // decoder gemm K-split partials
__device__ float d_ci[(size_t)NB*NT*CIW];
__device__ float d_hid[(size_t)NB*NT*H2];
__device__ unsigned int g_bar = 0;

__device__ __forceinline__ float sigf(float x) { return 1.f / (1.f + expf(-x)); }

// Software grid barrier. All GRID_PERS blocks must be co-resident.
__device__ __forceinline__ void grid_bar() {
    __syncthreads();
    if (threadIdx.x == 0) {
        __threadfence();                       // release
        unsigned int t = atomicAdd(&g_bar, 1u);
        unsigned int target = t - (t & (GRID_PERS - 1u)) + GRID_PERS;
        unsigned int v;
        do {
            asm volatile("ld.acquire.gpu.global.u32 %0, [%1];"
                         : "=r"(v) : "l"(&g_bar) : "memory");
        } while (v < target);
    }
    __syncthreads();
}

__device__ __forceinline__ uint32_t f2tf32(float f) {
    uint32_t r;
    asm("cvt.rna.tf32.f32 %0, %1;" : "=r"(r) : "f"(f));
    return r;
}

// ---------------------------------------------------------------------------
// tf32 mma.sync GEMM: C[M,N] = A[M,K] @ B[K,N] (+bias)(+relu)
// M%128==0, N%128==0, K%32==0. 256 threads = 8 warps (2m x 4n), warp 64x32.
// Fragment-packed double-buffered smem: tf32 cvt once per element at pack
// time; A frags = LDS.128, B frags = LDS.64, conflict-free.
// Dynamic smem = 2 * (16KB A_pack + 16KB B_pack) = 64KB.
// ---------------------------------------------------------------------------
#define MMAG_SMEM 65536

__global__ void __launch_bounds__(256)
mma_gemm_kernel(const float* __restrict__ A, const float* __restrict__ Bm,
                const float* __restrict__ bias, float* __restrict__ C,
                int M, int N, int K, int lda, int ldb, int ldc, int relu) {
    extern __shared__ uint32_t smu[];       // [2][8192]: A_pack[4096] B_pack[4096]
    int tid = threadIdx.x;
    int wid = tid >> 5, lane = tid & 31;
    int warp_m = wid & 1, warp_n = wid >> 1;
    int g = lane >> 2, t = lane & 3;
    int row0 = blockIdx.x * 128, col0 = blockIdx.y * 128;

    float acc[4][4][4];
#pragma unroll
    for (int i = 0; i < 4; i++)
#pragma unroll
        for (int j = 0; j < 4; j++)
#pragma unroll
            for (int f = 0; f < 4; f++) acc[i][j][f] = 0.f;

    float ra[16], rb[16];
    // A: thread owns fragment slots (ks=i, mt=wid, lane) for i in 0..3
    //    frag f: m = wid*16 + (f&1)*8 + g ; k = i*8 + (f>>1)*4 + t
    const float* Arow0 = A + (size_t)(row0 + wid * 16 + g) * lda;
    const float* Arow1 = Arow0 + (size_t)8 * lda;
    // B: slots (i): ks=i>>1, nt=(i&1)*8+wid; frag f: k=ks*8+f*4+t, n=nt*8+g
    const float* Bbase = Bm + col0;

    int NC = K >> 5;

    // ---- prologue: load + pack chunk 0
    {
#pragma unroll
        for (int i = 0; i < 4; i++)
#pragma unroll
            for (int f = 0; f < 4; f++) {
                int k = i * 8 + (f >> 1) * 4 + t;
                ra[i * 4 + f] = (f & 1) ? Arow1[k] : Arow0[k];
            }
#pragma unroll
        for (int i = 0; i < 8; i++) {
            int kk = (i >> 1) * 8 + t;
            int n = ((i & 1) * 8 + wid) * 8 + g;
            rb[i * 2 + 0] = Bbase[(size_t)kk * ldb + n];
            rb[i * 2 + 1] = Bbase[(size_t)(kk + 4) * ldb + n];
        }
        uint32_t* sb = smu;
#pragma unroll
        for (int i = 0; i < 4; i++) {
            uint4 u;
            u.x = f2tf32(ra[i*4+0]); u.y = f2tf32(ra[i*4+1]);
            u.z = f2tf32(ra[i*4+2]); u.w = f2tf32(ra[i*4+3]);
            ((uint4*)sb)[(i * 8 + wid) * 32 + lane] = u;
        }
#pragma unroll
        for (int i = 0; i < 8; i++) {
            uint2 u;
            u.x = f2tf32(rb[i*2+0]); u.y = f2tf32(rb[i*2+1]);
            ((uint2*)(sb + 4096))[(i * 8 + wid) * 32 + lane] = u;
        }
    }
    __syncthreads();

    for (int c = 0; c < NC; c++) {
        // issue next chunk's global loads early
        if (c + 1 < NC) {
            int kb = (c + 1) * 32;
#pragma unroll
            for (int i = 0; i < 4; i++)
#pragma unroll
                for (int f = 0; f < 4; f++) {
                    int k = kb + i * 8 + (f >> 1) * 4 + t;
                    ra[i * 4 + f] = (f & 1) ? Arow1[k] : Arow0[k];
                }
#pragma unroll
            for (int i = 0; i < 8; i++) {
                int kk = kb + (i >> 1) * 8 + t;
                int n = ((i & 1) * 8 + wid) * 8 + g;
                rb[i * 2 + 0] = Bbase[(size_t)kk * ldb + n];
                rb[i * 2 + 1] = Bbase[(size_t)(kk + 4) * ldb + n];
            }
        }

        // compute on buffer c&1
        {
            const uint32_t* sb = smu + (c & 1) * 8192;
            const uint4* Ap = (const uint4*)sb;
            const uint2* Bp = (const uint2*)(sb + 4096);
#pragma unroll
            for (int ks = 0; ks < 4; ks++) {
                uint4 aF[4];
                uint2 bF[4];
#pragma unroll
                for (int mt = 0; mt < 4; mt++)
                    aF[mt] = Ap[(ks * 8 + warp_m * 4 + mt) * 32 + lane];
#pragma unroll
                for (int nt = 0; nt < 4; nt++)
                    bF[nt] = Bp[(ks * 16 + warp_n * 4 + nt) * 32 + lane];
#pragma unroll
                for (int mt = 0; mt < 4; mt++)
#pragma unroll
                    for (int nt = 0; nt < 4; nt++) {
                        asm volatile(
                            "mma.sync.aligned.m16n8k8.row.col.f32.tf32.tf32.f32 "
                            "{%0,%1,%2,%3}, {%4,%5,%6,%7}, {%8,%9}, {%0,%1,%2,%3};"
                            : "+f"(acc[mt][nt][0]), "+f"(acc[mt][nt][1]),
                              "+f"(acc[mt][nt][2]), "+f"(acc[mt][nt][3])
                            : "r"(aF[mt].x), "r"(aF[mt].y),
                              "r"(aF[mt].z), "r"(aF[mt].w),
                              "r"(bF[nt].x), "r"(bF[nt].y));
                    }
            }
        }

        // pack next chunk into the other buffer
        if (c + 1 < NC) {
            uint32_t* sb = smu + ((c + 1) & 1) * 8192;
#pragma unroll
            for (int i = 0; i < 4; i++) {
                uint4 u;
                u.x = f2tf32(ra[i*4+0]); u.y = f2tf32(ra[i*4+1]);
                u.z = f2tf32(ra[i*4+2]); u.w = f2tf32(ra[i*4+3]);
                ((uint4*)sb)[(i * 8 + wid) * 32 + lane] = u;
            }
#pragma unroll
            for (int i = 0; i < 8; i++) {
                uint2 u;
                u.x = f2tf32(rb[i*2+0]); u.y = f2tf32(rb[i*2+1]);
                ((uint2*)(sb + 4096))[(i * 8 + wid) * 32 + lane] = u;
            }
        }
        __syncthreads();
    }

    // ---- epilogue
#pragma unroll
    for (int mt = 0; mt < 4; mt++) {
        int r = row0 + warp_m * 64 + mt * 16 + g;
#pragma unroll
        for (int nt = 0; nt < 4; nt++) {
            int cc = col0 + warp_n * 32 + nt * 8 + t * 2;
            float2 v0, v1;
            v0.x = acc[mt][nt][0]; v0.y = acc[mt][nt][1];
            v1.x = acc[mt][nt][2]; v1.y = acc[mt][nt][3];
            if (bias) {
                float b0 = bias[cc], b1 = bias[cc + 1];
                v0.x += b0; v0.y += b1; v1.x += b0; v1.y += b1;
            }
            if (relu) {
                v0.x = fmaxf(v0.x, 0.f); v0.y = fmaxf(v0.y, 0.f);
                v1.x = fmaxf(v1.x, 0.f); v1.y = fmaxf(v1.y, 0.f);
            }
            *(float2*)(C + (size_t)r * ldc + cc) = v0;
            *(float2*)(C + (size_t)(r + 8) * ldc + cc) = v1;
        }
    }
}

// ---------------------------------------------------------------------------
// Zero / gather
// ---------------------------------------------------------------------------
__global__ void zero_state_kernel() {
    int i = blockIdx.x * 256 + threadIdx.x;
    if (i < 2*4*NB*NH) ((float*)d_hbuf)[i] = 0.f;
}

__global__ void gather_kernel(const int* __restrict__ src_ids,
                              const int* __restrict__ tgt_ids,
                              const int* __restrict__ rat_ids,
                              const float* __restrict__ src_emb,
                              const float* __restrict__ tgt_emb) {
    int tok = blockIdx.x;          // s*64 + b
    int set = blockIdx.y;          // 0 src, 1 rat, 2 tgt
    int s = tok >> 6, b = tok & 63;
    int id;
    const float* emb;
    float* out;
    if (set == 0)      { id = src_ids[b*NS + s]; emb = src_emb; out = d_src_e; }
    else if (set == 1) { id = rat_ids[b*NS + s]; emb = src_emb; out = d_rat_e; }
    else               { id = tgt_ids[b*NT + s]; emb = tgt_emb; out = d_tgt_e; }
    const float* row = emb + (size_t)id * NE;
    float* dst = out + (size_t)tok * NE;
    for (int e = threadIdx.x; e < NE; e += 256) dst[e] = row[e];
}

// ---------------------------------------------------------------------------
// Persistent encoder: all 64 steps, 4 LSTMs, one kernel. (unchanged)
// ---------------------------------------------------------------------------
__global__ void __launch_bounds__(256)
enc_persistent_kernel(const float* __restrict__ Whh_f,
                      const float* __restrict__ Whh_b) {
    __shared__ float As[16][64];
    __shared__ float Bs[16][68];
    __shared__ float gsm[64][68];
    __shared__ float cs[64][16];
    int blk = blockIdx.x;
    int l = blk >> 5;                 // lstm id {srcF,srcB,ratF,ratB}
    int j0 = (blk & 31) * 16;         // unit-tile base
    const float* Whh = (l & 1) ? Whh_b : Whh_f;
    int tid = threadIdx.x;
    int tx = tid & 15, ty = tid >> 4;

    for (int p = tid; p < 1024; p += 256) ((float*)cs)[p] = 0.f;

    int aRow = tid >> 2, aCol = (tid & 3) * 4;
    int bRow = tid >> 4, bCol = tx * 4;
    const float* Bbase = Whh + (bCol >> 4) * NH + j0 + (bCol & 15);

    float* eo = (l < 2) ? d_enc[0] : d_enc[1];
    int half = (l & 1) * NH;

    for (int t = 0; t < NS; t++) {
        const float* h = d_hbuf[t & 1][l];
        float acc[4][4];
#pragma unroll
        for (int i = 0; i < 4; i++)
#pragma unroll
            for (int j = 0; j < 4; j++) acc[i][j] = 0.f;

        for (int kb = 0; kb < NH; kb += 16) {
            float4 va = __ldcg((const float4*)(h + aRow * NH + kb + aCol));
            As[aCol+0][aRow] = va.x; As[aCol+1][aRow] = va.y;
            As[aCol+2][aRow] = va.z; As[aCol+3][aRow] = va.w;
            float4 vb = *(const float4*)(Bbase + (size_t)(kb + bRow) * H4);
            *(float4*)&Bs[bRow][bCol] = vb;
            __syncthreads();
#pragma unroll
            for (int k = 0; k < 16; k++) {
                float a[4], b[4];
                *(float4*)a = *(float4*)&As[k][ty*4];
                *(float4*)b = *(float4*)&Bs[k][tx*4];
#pragma unroll
                for (int i = 0; i < 4; i++)
#pragma unroll
                    for (int j = 0; j < 4; j++) acc[i][j] = fmaf(a[i], b[j], acc[i][j]);
            }
            __syncthreads();
        }
#pragma unroll
        for (int i = 0; i < 4; i++)
            *(float4*)&gsm[ty*4 + i][tx*4] = *(float4*)&acc[i][0];
        __syncthreads();

        int tX = (l & 1) ? (NS - 1 - t) : t;
        const float* xw = d_Xw[l] + (size_t)(tX * NB) * H4;
        float* hn = d_hbuf[(t + 1) & 1][l];
        for (int p = tid; p < 1024; p += 256) {
            int m = p >> 4, jj = p & 15;
            int j = j0 + jj;
            const float* xr = xw + (size_t)m * H4;
            float gi = gsm[m][jj]      + xr[j];
            float gf = gsm[m][16 + jj] + xr[NH + j];
            float gg = gsm[m][32 + jj] + xr[2*NH + j];
            float go = gsm[m][48 + jj] + xr[3*NH + j];
            float cp = cs[m][jj];
            float cn = sigf(gf) * cp + sigf(gi) * tanhf(gg);
            float hv = sigf(go) * tanhf(cn);
            cs[m][jj] = cn;
            hn[m*NH + j] = hv;
            eo[((size_t)m * NS + tX) * H2 + half + j] = hv;
        }
        grid_bar();
    }
    // dump (src,fwd) final c for decoder init
    if (l == 0) {
        for (int p = tid; p < 1024; p += 256) {
            int m = p >> 4, jj = p & 15;
            d_cfin[m*NH + j0 + jj] = cs[m][jj];
        }
    }
}

// ---------------------------------------------------------------------------
// Persistent decoder: all 32 steps, one kernel, 4 phases/step. (unchanged)
// ---------------------------------------------------------------------------
__global__ void __launch_bounds__(256)
dec_persistent_kernel(const float* __restrict__ dec_Wih,
                      const float* __restrict__ dec_Whh,
                      const float* __restrict__ att_W1,
                      const float* __restrict__ att_W2,
                      const float* __restrict__ att_b2) {
    __shared__ float As[16][64];
    __shared__ float Bs[16][68];
    __shared__ float Bq[16][17];
    __shared__ float qs[H3];
    __shared__ float w2s[H3];
    __shared__ float logits[NS];
    __shared__ float wts[NS];
    __shared__ float sred[2];

    int blk = blockIdx.x, tid = threadIdx.x;
    int tx = tid & 15, ty = tid >> 4;
    int aRow = tid >> 2, aCol = (tid & 3) * 4;

    int p = blk * 256 + tid;           // 0..32767
    int pm = p >> 9, pj = p & 511;
    float c_reg = d_cfin[pm * NH + pj];

    for (int t = 0; t < NSTEPS; t++) {
        const float* h = (t == 0) ? d_hbuf[0][0] : d_hdec[t & 1];

        // ---- Phase 1: q[64,1536] = h[64,512] @ W1[1024:1536, :]
        if (blk < 96) {
            int c0 = blk * 16;
            float acc[4] = {0.f, 0.f, 0.f, 0.f};
            for (int kb = 0; kb < NH; kb += 16) {
                float4 va = __ldcg((const float4*)(h + aRow * NH + kb + aCol));
                As[aCol+0][aRow] = va.x; As[aCol+1][aRow] = va.y;
                As[aCol+2][aRow] = va.z; As[aCol+3][aRow] = va.w;
                Bq[tid >> 4][tid & 15] =
                    att_W1[(size_t)(H2 + kb + (tid >> 4)) * H3 + c0 + (tid & 15)];
                __syncthreads();
#pragma unroll
                for (int k = 0; k < 16; k++) {
                    float b = Bq[k][tx];
#pragma unroll
                    for (int i = 0; i < 4; i++)
                        acc[i] = fmaf(As[k][ty*4 + i], b, acc[i]);
                }
                __syncthreads();
            }
#pragma unroll
            for (int i = 0; i < 4; i++)
                d_q[(ty*4 + i) * H3 + c0 + tx] = acc[i];
        }
        grid_bar();

        // ---- Phase 2: attention (both encoders)
        {
            int b = blk & 63, e = blk >> 6;
            const float* P   = d_P[e] + (size_t)(b * NS) * H3;
            const float* enc = d_enc[e] + (size_t)(b * NS) * H2;
            for (int j2 = tid; j2 < H3; j2 += 256) {
                qs[j2]  = __ldcg(&d_q[b * H3 + j2]);
                w2s[j2] = att_W2[j2];
            }
            __syncthreads();
            int w = tid >> 5, lane = tid & 31;
            float b2v = att_b2[0];
#pragma unroll
            for (int si = 0; si < 8; si++) {
                int s = w * 8 + si;
                const float* Pr = P + (size_t)s * H3;
                float part = 0.f;
                for (int j2 = lane; j2 < H3; j2 += 32)
                    part += fmaxf(Pr[j2] + qs[j2], 0.f) * w2s[j2];
#pragma unroll
                for (int off = 16; off; off >>= 1)
                    part += __shfl_down_sync(0xffffffffu, part, off);
                if (lane == 0) logits[s] = part + b2v;
            }
            __syncthreads();
            if (tid == 0) {
                float mx = -1e30f;
                for (int s = 0; s < NS; s++) mx = fmaxf(mx, logits[s]);
                sred[0] = mx;
            }
            __syncthreads();
            if (tid < NS) wts[tid] = expf(logits[tid] - sred[0]);
            __syncthreads();
            if (tid == 0) {
                float sm = 0.f;
                for (int s = 0; s < NS; s++) sm += wts[s];
                sred[1] = 1.f / sm;
            }
            __syncthreads();
            float inv = sred[1];
            float* outA = d_Abuf[e] + (size_t)(t * NB + b) * H2;
            for (int ch = tid; ch < H2; ch += 256) {
                float a = 0.f;
                for (int s = 0; s < NS; s++)
                    a += wts[s] * enc[(size_t)s * H2 + ch];
                outA[ch] = a * inv;
            }
        }
        grid_bar();

        // ---- Phase 3: dec gemm partials: [A,Ar,h] @ [Wih[512:],Whh], K split x4
        {
            int ks = blk >> 5, ct = blk & 31;
            int c0 = ct * 64;
            const float* Ab  = d_Abuf[0] + (size_t)(t * NB) * H2;
            const float* Arb = d_Abuf[1] + (size_t)(t * NB) * H2;
            float acc[4][4];
#pragma unroll
            for (int i = 0; i < 4; i++)
#pragma unroll
                for (int j = 0; j < 4; j++) acc[i][j] = 0.f;

            int k0 = ks * 640;
            for (int kb = k0; kb < k0 + 640; kb += 16) {
                const float* asrc; int stride, koff;
                if (kb < 1024)      { asrc = Ab;  stride = H2; koff = kb; }
                else if (kb < 2048) { asrc = Arb; stride = H2; koff = kb - 1024; }
                else                { asrc = h;   stride = NH; koff = kb - 2048; }
                float4 va = __ldcg((const float4*)(asrc + (size_t)aRow * stride + koff + aCol));
                As[aCol+0][aRow] = va.x; As[aCol+1][aRow] = va.y;
                As[aCol+2][aRow] = va.z; As[aCol+3][aRow] = va.w;
                int kk = kb + (tid >> 4);
                const float* Brow = (kk < 2048) ? (dec_Wih + (size_t)(NE + kk) * H4)
                                                : (dec_Whh + (size_t)(kk - 2048) * H4);
                *(float4*)&Bs[tid >> 4][tx * 4] = *(const float4*)(Brow + c0 + tx * 4);
                __syncthreads();
#pragma unroll
                for (int k = 0; k < 16; k++) {
                    float a[4], b[4];
                    *(float4*)a = *(float4*)&As[k][ty*4];
                    *(float4*)b = *(float4*)&Bs[k][tx*4];
#pragma unroll
                    for (int i = 0; i < 4; i++)
#pragma unroll
                        for (int j = 0; j < 4; j++) acc[i][j] = fmaf(a[i], b[j], acc[i][j]);
                }
                __syncthreads();
            }
            float* gp = d_gpart + (size_t)(ks * NB) * H4;
#pragma unroll
            for (int i = 0; i < 4; i++)
                *(float4*)(gp + (size_t)(ty*4 + i) * H4 + c0 + tx*4) = *(float4*)&acc[i][0];
        }
        grid_bar();

        // ---- Phase 4: gates (1 thread per (m,j))
        {
            const float* xr = d_tgtW + (size_t)(t * NB + pm) * H4;
            float g4[4];
#pragma unroll
            for (int g = 0; g < 4; g++) {
                float v = xr[g * NH + pj];
#pragma unroll
                for (int ks = 0; ks < 4; ks++)
                    v += __ldcg(&d_gpart[(size_t)(ks * NB + pm) * H4 + g * NH + pj]);
                g4[g] = v;
            }
            float cn = sigf(g4[1]) * c_reg + sigf(g4[0]) * tanhf(g4[2]);
            float hv = sigf(g4[3]) * tanhf(cn);
            c_reg = cn;
            d_hdec[(t + 1) & 1][pm * NH + pj] = hv;
            d_Dbuf[((size_t)t * NB + pm) * NH + pj] = hv;
        }
        grid_bar();
    }
}

// ---------------------------------------------------------------------------
// Assemble classifier input ci[r=b*T+t] = [tgt_e, A, Ar, g, D] (zeros past STEPS)
// ---------------------------------------------------------------------------
__global__ void assemble_kernel(const float* __restrict__ graph_embs) {
    int r = blockIdx.x;
    int b = r >> 6, t = r & 63;
    float* row = d_ci + (size_t)r * CIW;
    bool live = (t < NSTEPS);
    for (int c = threadIdx.x; c < CIW; c += 256) {
        float v;
        if (c < 512)       v = d_tgt_e[((size_t)t * NB + b) * NE + c];
        else if (c < 1536) v = live ? d_Abuf[0][((size_t)t * NB + b) * H2 + (c - 512)]  : 0.f;
        else if (c < 2560) v = live ? d_Abuf[1][((size_t)t * NB + b) * H2 + (c - 1536)] : 0.f;
        else if (c < 2816) v = graph_embs[b * NG + (c - 2560)];
        else               v = live ? d_Dbuf[((size_t)t * NB + b) * NH + (c - 2816)]    : 0.f;
        row[c] = v;
    }
}

// ---------------------------------------------------------------------------
// Host launch
// ---------------------------------------------------------------------------
static float* symaddr(const void* s) {
    void* p = nullptr;
    cudaGetSymbolAddress(&p, s);
    return (float*)p;
}

static void gemm_mma(const float* A, const float* B, const float* bias, float* C,
                     int M, int N, int K, int lda, int ldb, int ldc, int relu) {
    dim3 g(M / 128, N / 128);   // x = M tiles (adjacent CTAs share the B band)
    mma_gemm_kernel<<<g, 256, MMAG_SMEM>>>(A, B, bias, C, M, N, K, lda, ldb, ldc, relu);
}

extern "C" void kernel_launch(void* const* d_in, const int* in_sizes, int n_in,
                              void* d_out, int out_size) {
    const int*   source_data = (const int*)d_in[0];
    const int*   target_data = (const int*)d_in[1];
    const int*   rationales  = (const int*)d_in[2];
    const float* graph_embs  = (const float*)d_in[3];
    const float* src_emb     = (const float*)d_in[4];
    const float* tgt_emb     = (const float*)d_in[5];
    const float* enc_Wih_f   = (const float*)d_in[6];
    const float* enc_Whh_f   = (const float*)d_in[7];
    const float* enc_b_f     = (const float*)d_in[8];
    const float* enc_Wih_b   = (const float*)d_in[9];
    const float* enc_Whh_b   = (const float*)d_in[10];
    const float* enc_b_b     = (const float*)d_in[11];
    const float* dec_Wih     = (const float*)d_in[12];
    const float* dec_Whh     = (const float*)d_in[13];
    const float* dec_b       = (const float*)d_in[14];
    const float* att_W1      = (const float*)d_in[15];
    const float* att_b1      = (const float*)d_in[16];
    const float* att_W2      = (const float*)d_in[17];
    const float* att_b2      = (const float*)d_in[18];
    const float* cls_Wg      = (const float*)d_in[19];
    const float* cls_bg      = (const float*)d_in[20];
    const float* cls_W2      = (const float*)d_in[21];
    const float* cls_b2      = (const float*)d_in[22];
    float* out = (float*)d_out;

    cudaFuncSetAttribute(mma_gemm_kernel,
                         cudaFuncAttributeMaxDynamicSharedMemorySize, MMAG_SMEM);

    float* p_src_e = symaddr(d_src_e);
    float* p_rat_e = symaddr(d_rat_e);
    float* p_tgt_e = symaddr(d_tgt_e);
    float* p_Xw    = symaddr(d_Xw);
    float* p_enc   = symaddr(d_enc);
    float* p_P     = symaddr(d_P);
    float* p_tgtW  = symaddr(d_tgtW);
    float* p_ci    = symaddr(d_ci);
    float* p_hid   = symaddr(d_hid);
    void*  p_bar   = nullptr;
    cudaGetSymbolAddress(&p_bar, g_bar);

    const size_t XW  = (size_t)NS * NB * H4;
    const size_t ENC = (size_t)NB * NS * H2;
    const size_t PP  = (size_t)NB * NS * H3;

    cudaMemsetAsync(p_bar, 0, sizeof(unsigned int));
    zero_state_kernel<<<1024, 256>>>();
    gather_kernel<<<dim3(4096, 3), 256>>>(source_data, target_data, rationales,
                                          src_emb, tgt_emb);

    // x @ Wih + b, hoisted for all 4 encoder LSTMs (tf32 mma)
    gemm_mma(p_src_e, enc_Wih_f, enc_b_f, p_Xw + 0*XW, 4096, H4, NE, NE, H4, H4, 0);
    gemm_mma(p_src_e, enc_Wih_b, enc_b_b, p_Xw + 1*XW, 4096, H4, NE, NE, H4, H4, 0);
    gemm_mma(p_rat_e, enc_Wih_f, enc_b_f, p_Xw + 2*XW, 4096, H4, NE, NE, H4, H4, 0);
    gemm_mma(p_rat_e, enc_Wih_b, enc_b_b, p_Xw + 3*XW, 4096, H4, NE, NE, H4, H4, 0);

    // tgt_e @ dec_Wih[:E] + dec_b, hoisted for all 32 decoder steps
    gemm_mma(p_tgt_e, dec_Wih, dec_b, p_tgtW, NSTEPS * NB, H4, NE, NE, H4, H4, 0);

    // encoder recurrence: one persistent kernel, 64 steps
    enc_persistent_kernel<<<GRID_PERS, 256>>>(enc_Whh_f, enc_Whh_b);

    // attention pre-projection: enc_out @ W1[:2H] + b1
    gemm_mma(p_enc + 0*ENC, att_W1, att_b1, p_P + 0*PP, 4096, H3, H2, H2, H3, H3, 0);
    gemm_mma(p_enc + 1*ENC, att_W1, att_b1, p_P + 1*PP, 4096, H3, H2, H2, H3, H3, 0);

    // decoder recurrence: one persistent kernel, 32 steps
    dec_persistent_kernel<<<GRID_PERS, 256>>>(dec_Wih, dec_Whh,
                                              att_W1, att_W2, att_b2);

    // classifier (tf32 mma)
    assemble_kernel<<<4096, 256>>>(graph_embs);
    gemm_mma(p_ci,  cls_Wg, cls_bg, p_hid, 4096, H2, CIW, CIW, H2, H2, 1);
    gemm_mma(p_hid, cls_W2, cls_b2, out,   4096, NV,  H2,  H2, NV, NV, 0);
}

// round 7
// speedup vs baseline: 2.7035x; 1.0472x over previous
#include <cuda_runtime.h>
#include <math.h>
#include <stdint.h>

// ---------------------------------------------------------------------------
// Problem constants: B=64, S=64, T=64, STEPS=32, E=512, H=512, G=256, V=32000
// ---------------------------------------------------------------------------
#define NB   64
#define NS   64
#define NT   64
#define NSTEPS 32
#define NE   512
#define NH   512
#define NG   256
#define NV   32000
#define H4   2048
#define H2   1024
#define H3   1536
#define CIW  3328   // E + 2H + 2H + G + H

#define GRID_PERS 128   // persistent-kernel grid (<=148 SMs -> co-resident)

// ---------------------------------------------------------------------------
// Scratch (device globals; no allocations allowed)
// ---------------------------------------------------------------------------
__device__ float d_src_e[NS*NB*NE];        // time-major [s][b][e]
__device__ float d_rat_e[NS*NB*NE];
__device__ float d_tgt_e[NT*NB*NE];        // [t][b][e]
__device__ float d_Xw[4][NS*NB*H4];        // x@Wih + b per lstm {srcF,srcB,ratF,ratB}
__device__ float d_hbuf[2][4][NB*NH];      // ping-pong h (encoder)
__device__ float d_enc[2][NB*NS*H2];       // [b][s][2H]; 0=src 1=rat
__device__ float d_P[2][NB*NS*H3];         // enc_out @ W1[:2H] + b1
__device__ float d_q[NB*H3];               // h @ W1[2H:]
__device__ float d_Abuf[2][NSTEPS*NB*H2];  // attention outputs A, Ar
__device__ float d_Dbuf[NSTEPS*NB*NH];     // decoder h per step
__device__ float d_tgtW[NSTEPS*NB*H4];     // tgt_e @ dec_Wih[:E] + dec_b
__device__ float d_hdec[2][NB*NH];
__device__ float d_cfin[NB*NH];            // encoder (src,fwd) final c
__device__ float d_gpart[4*NB*H4];         // decoder gemm K-split partials
__device__ float d_ci[(size_t)NB*NT*CIW];
__device__ float d_hid[(size_t)NB*NT*H2];
__device__ unsigned int g_bar = 0;

__device__ __forceinline__ float sigf(float x) { return 1.f / (1.f + expf(-x)); }

// Software grid barrier. All GRID_PERS blocks must be co-resident.
__device__ __forceinline__ void grid_bar() {
    __syncthreads();
    if (threadIdx.x == 0) {
        __threadfence();                       // release
        unsigned int t = atomicAdd(&g_bar, 1u);
        unsigned int target = t - (t & (GRID_PERS - 1u)) + GRID_PERS;
        unsigned int v;
        do {
            asm volatile("ld.acquire.gpu.global.u32 %0, [%1];"
                         : "=r"(v) : "l"(&g_bar) : "memory");
        } while (v < target);
    }
    __syncthreads();
}

__device__ __forceinline__ uint32_t f2tf32(float f) {
    uint32_t r;
    asm("cvt.rna.tf32.f32 %0, %1;" : "=r"(r) : "f"(f));
    return r;
}

// ---------------------------------------------------------------------------
// tf32 mma.sync GEMM: C[M,N] = A[M,K] @ B[K,N] (+bias)(+relu)
// M%128==0, N%128==0, K%32==0. 256 threads = 8 warps (2m x 4n), warp 64x32.
// Fragment-packed double-buffered smem; __launch_bounds__(256,2) caps regs at
// 128 so TWO CTAs fit per SM (was 130 regs -> 1 CTA -> 12.5% occ).
// Dynamic smem = 2 * (16KB A_pack + 16KB B_pack) = 64KB (2 CTAs = 128KB/SM).
// ---------------------------------------------------------------------------
#define MMAG_SMEM 65536

__global__ void __launch_bounds__(256, 2)
mma_gemm_kernel(const float* __restrict__ A, const float* __restrict__ Bm,
                const float* __restrict__ bias, float* __restrict__ C,
                int M, int N, int K, int lda, int ldb, int ldc, int relu) {
    extern __shared__ uint32_t smu[];       // [2][8192]: A_pack[4096] B_pack[4096]
    int tid = threadIdx.x;
    int wid = tid >> 5, lane = tid & 31;
    int warp_m = wid & 1, warp_n = wid >> 1;
    int g = lane >> 2, t = lane & 3;
    int row0 = blockIdx.x * 128, col0 = blockIdx.y * 128;

    float acc[4][4][4];
#pragma unroll
    for (int i = 0; i < 4; i++)
#pragma unroll
        for (int j = 0; j < 4; j++)
#pragma unroll
            for (int f = 0; f < 4; f++) acc[i][j][f] = 0.f;

    float ra[16], rb[16];
    // A: thread owns fragment slots (ks=i, mt=wid, lane) for i in 0..3
    //    frag f: m = wid*16 + (f&1)*8 + g ; k = i*8 + (f>>1)*4 + t
    const float* Arow0 = A + (size_t)(row0 + wid * 16 + g) * lda;
    const float* Arow1 = Arow0 + (size_t)8 * lda;
    // B: slots (i): ks=i>>1, nt=(i&1)*8+wid; frag f: k=ks*8+f*4+t, n=nt*8+g
    const float* Bbase = Bm + col0;

    int NC = K >> 5;

    // ---- prologue: load + pack chunk 0
    {
#pragma unroll
        for (int i = 0; i < 4; i++)
#pragma unroll
            for (int f = 0; f < 4; f++) {
                int k = i * 8 + (f >> 1) * 4 + t;
                ra[i * 4 + f] = (f & 1) ? Arow1[k] : Arow0[k];
            }
#pragma unroll
        for (int i = 0; i < 8; i++) {
            int kk = (i >> 1) * 8 + t;
            int n = ((i & 1) * 8 + wid) * 8 + g;
            rb[i * 2 + 0] = Bbase[(size_t)kk * ldb + n];
            rb[i * 2 + 1] = Bbase[(size_t)(kk + 4) * ldb + n];
        }
        uint32_t* sb = smu;
#pragma unroll
        for (int i = 0; i < 4; i++) {
            uint4 u;
            u.x = f2tf32(ra[i*4+0]); u.y = f2tf32(ra[i*4+1]);
            u.z = f2tf32(ra[i*4+2]); u.w = f2tf32(ra[i*4+3]);
            ((uint4*)sb)[(i * 8 + wid) * 32 + lane] = u;
        }
#pragma unroll
        for (int i = 0; i < 8; i++) {
            uint2 u;
            u.x = f2tf32(rb[i*2+0]); u.y = f2tf32(rb[i*2+1]);
            ((uint2*)(sb + 4096))[(i * 8 + wid) * 32 + lane] = u;
        }
    }
    __syncthreads();

    for (int c = 0; c < NC; c++) {
        // issue next chunk's global loads early
        if (c + 1 < NC) {
            int kb = (c + 1) * 32;
#pragma unroll
            for (int i = 0; i < 4; i++)
#pragma unroll
                for (int f = 0; f < 4; f++) {
                    int k = kb + i * 8 + (f >> 1) * 4 + t;
                    ra[i * 4 + f] = (f & 1) ? Arow1[k] : Arow0[k];
                }
#pragma unroll
            for (int i = 0; i < 8; i++) {
                int kk = kb + (i >> 1) * 8 + t;
                int n = ((i & 1) * 8 + wid) * 8 + g;
                rb[i * 2 + 0] = Bbase[(size_t)kk * ldb + n];
                rb[i * 2 + 1] = Bbase[(size_t)(kk + 4) * ldb + n];
            }
        }

        // compute on buffer c&1
        {
            const uint32_t* sb = smu + (c & 1) * 8192;
            const uint4* Ap = (const uint4*)sb;
            const uint2* Bp = (const uint2*)(sb + 4096);
#pragma unroll
            for (int ks = 0; ks < 4; ks++) {
                uint4 aF[4];
                uint2 bF[4];
#pragma unroll
                for (int mt = 0; mt < 4; mt++)
                    aF[mt] = Ap[(ks * 8 + warp_m * 4 + mt) * 32 + lane];
#pragma unroll
                for (int nt = 0; nt < 4; nt++)
                    bF[nt] = Bp[(ks * 16 + warp_n * 4 + nt) * 32 + lane];
#pragma unroll
                for (int mt = 0; mt < 4; mt++)
#pragma unroll
                    for (int nt = 0; nt < 4; nt++) {
                        asm volatile(
                            "mma.sync.aligned.m16n8k8.row.col.f32.tf32.tf32.f32 "
                            "{%0,%1,%2,%3}, {%4,%5,%6,%7}, {%8,%9}, {%0,%1,%2,%3};"
                            : "+f"(acc[mt][nt][0]), "+f"(acc[mt][nt][1]),
                              "+f"(acc[mt][nt][2]), "+f"(acc[mt][nt][3])
                            : "r"(aF[mt].x), "r"(aF[mt].y),
                              "r"(aF[mt].z), "r"(aF[mt].w),
                              "r"(bF[nt].x), "r"(bF[nt].y));
                    }
            }
        }

        // pack next chunk into the other buffer
        if (c + 1 < NC) {
            uint32_t* sb = smu + ((c + 1) & 1) * 8192;
#pragma unroll
            for (int i = 0; i < 4; i++) {
                uint4 u;
                u.x = f2tf32(ra[i*4+0]); u.y = f2tf32(ra[i*4+1]);
                u.z = f2tf32(ra[i*4+2]); u.w = f2tf32(ra[i*4+3]);
                ((uint4*)sb)[(i * 8 + wid) * 32 + lane] = u;
            }
#pragma unroll
            for (int i = 0; i < 8; i++) {
                uint2 u;
                u.x = f2tf32(rb[i*2+0]); u.y = f2tf32(rb[i*2+1]);
                ((uint2*)(sb + 4096))[(i * 8 + wid) * 32 + lane] = u;
            }
        }
        __syncthreads();
    }

    // ---- epilogue
#pragma unroll
    for (int mt = 0; mt < 4; mt++) {
        int r = row0 + warp_m * 64 + mt * 16 + g;
#pragma unroll
        for (int nt = 0; nt < 4; nt++) {
            int cc = col0 + warp_n * 32 + nt * 8 + t * 2;
            float2 v0, v1;
            v0.x = acc[mt][nt][0]; v0.y = acc[mt][nt][1];
            v1.x = acc[mt][nt][2]; v1.y = acc[mt][nt][3];
            if (bias) {
                float b0 = bias[cc], b1 = bias[cc + 1];
                v0.x += b0; v0.y += b1; v1.x += b0; v1.y += b1;
            }
            if (relu) {
                v0.x = fmaxf(v0.x, 0.f); v0.y = fmaxf(v0.y, 0.f);
                v1.x = fmaxf(v1.x, 0.f); v1.y = fmaxf(v1.y, 0.f);
            }
            *(float2*)(C + (size_t)r * ldc + cc) = v0;
            *(float2*)(C + (size_t)(r + 8) * ldc + cc) = v1;
        }
    }
}

// ---------------------------------------------------------------------------
// Zero / gather
// ---------------------------------------------------------------------------
__global__ void zero_state_kernel() {
    int i = blockIdx.x * 256 + threadIdx.x;
    if (i < 2*4*NB*NH) ((float*)d_hbuf)[i] = 0.f;
}

__global__ void gather_kernel(const int* __restrict__ src_ids,
                              const int* __restrict__ tgt_ids,
                              const int* __restrict__ rat_ids,
                              const float* __restrict__ src_emb,
                              const float* __restrict__ tgt_emb) {
    int tok = blockIdx.x;          // s*64 + b
    int set = blockIdx.y;          // 0 src, 1 rat, 2 tgt
    int s = tok >> 6, b = tok & 63;
    int id;
    const float* emb;
    float* out;
    if (set == 0)      { id = src_ids[b*NS + s]; emb = src_emb; out = d_src_e; }
    else if (set == 1) { id = rat_ids[b*NS + s]; emb = src_emb; out = d_rat_e; }
    else               { id = tgt_ids[b*NT + s]; emb = tgt_emb; out = d_tgt_e; }
    const float* row = emb + (size_t)id * NE;
    float* dst = out + (size_t)tok * NE;
    for (int e = threadIdx.x; e < NE; e += 256) dst[e] = row[e];
}

// ---------------------------------------------------------------------------
// Persistent encoder: all 64 steps, 4 LSTMs, one kernel. (unchanged)
// ---------------------------------------------------------------------------
__global__ void __launch_bounds__(256)
enc_persistent_kernel(const float* __restrict__ Whh_f,
                      const float* __restrict__ Whh_b) {
    __shared__ float As[16][64];
    __shared__ float Bs[16][68];
    __shared__ float gsm[64][68];
    __shared__ float cs[64][16];
    int blk = blockIdx.x;
    int l = blk >> 5;                 // lstm id {srcF,srcB,ratF,ratB}
    int j0 = (blk & 31) * 16;         // unit-tile base
    const float* Whh = (l & 1) ? Whh_b : Whh_f;
    int tid = threadIdx.x;
    int tx = tid & 15, ty = tid >> 4;

    for (int p = tid; p < 1024; p += 256) ((float*)cs)[p] = 0.f;

    int aRow = tid >> 2, aCol = (tid & 3) * 4;
    int bRow = tid >> 4, bCol = tx * 4;
    const float* Bbase = Whh + (bCol >> 4) * NH + j0 + (bCol & 15);

    float* eo = (l < 2) ? d_enc[0] : d_enc[1];
    int half = (l & 1) * NH;

    for (int t = 0; t < NS; t++) {
        const float* h = d_hbuf[t & 1][l];
        float acc[4][4];
#pragma unroll
        for (int i = 0; i < 4; i++)
#pragma unroll
            for (int j = 0; j < 4; j++) acc[i][j] = 0.f;

        for (int kb = 0; kb < NH; kb += 16) {
            float4 va = __ldcg((const float4*)(h + aRow * NH + kb + aCol));
            As[aCol+0][aRow] = va.x; As[aCol+1][aRow] = va.y;
            As[aCol+2][aRow] = va.z; As[aCol+3][aRow] = va.w;
            float4 vb = *(const float4*)(Bbase + (size_t)(kb + bRow) * H4);
            *(float4*)&Bs[bRow][bCol] = vb;
            __syncthreads();
#pragma unroll
            for (int k = 0; k < 16; k++) {
                float a[4], b[4];
                *(float4*)a = *(float4*)&As[k][ty*4];
                *(float4*)b = *(float4*)&Bs[k][tx*4];
#pragma unroll
                for (int i = 0; i < 4; i++)
#pragma unroll
                    for (int j = 0; j < 4; j++) acc[i][j] = fmaf(a[i], b[j], acc[i][j]);
            }
            __syncthreads();
        }
#pragma unroll
        for (int i = 0; i < 4; i++)
            *(float4*)&gsm[ty*4 + i][tx*4] = *(float4*)&acc[i][0];
        __syncthreads();

        int tX = (l & 1) ? (NS - 1 - t) : t;
        const float* xw = d_Xw[l] + (size_t)(tX * NB) * H4;
        float* hn = d_hbuf[(t + 1) & 1][l];
        for (int p = tid; p < 1024; p += 256) {
            int m = p >> 4, jj = p & 15;
            int j = j0 + jj;
            const float* xr = xw + (size_t)m * H4;
            float gi = gsm[m][jj]      + xr[j];
            float gf = gsm[m][16 + jj] + xr[NH + j];
            float gg = gsm[m][32 + jj] + xr[2*NH + j];
            float go = gsm[m][48 + jj] + xr[3*NH + j];
            float cp = cs[m][jj];
            float cn = sigf(gf) * cp + sigf(gi) * tanhf(gg);
            float hv = sigf(go) * tanhf(cn);
            cs[m][jj] = cn;
            hn[m*NH + j] = hv;
            eo[((size_t)m * NS + tX) * H2 + half + j] = hv;
        }
        grid_bar();
    }
    // dump (src,fwd) final c for decoder init
    if (l == 0) {
        for (int p = tid; p < 1024; p += 256) {
            int m = p >> 4, jj = p & 15;
            d_cfin[m*NH + j0 + jj] = cs[m][jj];
        }
    }
}

// ---------------------------------------------------------------------------
// Persistent decoder: all 32 steps, one kernel, 4 phases/step. (unchanged)
// ---------------------------------------------------------------------------
__global__ void __launch_bounds__(256)
dec_persistent_kernel(const float* __restrict__ dec_Wih,
                      const float* __restrict__ dec_Whh,
                      const float* __restrict__ att_W1,
                      const float* __restrict__ att_W2,
                      const float* __restrict__ att_b2) {
    __shared__ float As[16][64];
    __shared__ float Bs[16][68];
    __shared__ float Bq[16][17];
    __shared__ float qs[H3];
    __shared__ float w2s[H3];
    __shared__ float logits[NS];
    __shared__ float wts[NS];
    __shared__ float sred[2];

    int blk = blockIdx.x, tid = threadIdx.x;
    int tx = tid & 15, ty = tid >> 4;
    int aRow = tid >> 2, aCol = (tid & 3) * 4;

    int p = blk * 256 + tid;           // 0..32767
    int pm = p >> 9, pj = p & 511;
    float c_reg = d_cfin[pm * NH + pj];

    for (int t = 0; t < NSTEPS; t++) {
        const float* h = (t == 0) ? d_hbuf[0][0] : d_hdec[t & 1];

        // ---- Phase 1: q[64,1536] = h[64,512] @ W1[1024:1536, :]
        if (blk < 96) {
            int c0 = blk * 16;
            float acc[4] = {0.f, 0.f, 0.f, 0.f};
            for (int kb = 0; kb < NH; kb += 16) {
                float4 va = __ldcg((const float4*)(h + aRow * NH + kb + aCol));
                As[aCol+0][aRow] = va.x; As[aCol+1][aRow] = va.y;
                As[aCol+2][aRow] = va.z; As[aCol+3][aRow] = va.w;
                Bq[tid >> 4][tid & 15] =
                    att_W1[(size_t)(H2 + kb + (tid >> 4)) * H3 + c0 + (tid & 15)];
                __syncthreads();
#pragma unroll
                for (int k = 0; k < 16; k++) {
                    float b = Bq[k][tx];
#pragma unroll
                    for (int i = 0; i < 4; i++)
                        acc[i] = fmaf(As[k][ty*4 + i], b, acc[i]);
                }
                __syncthreads();
            }
#pragma unroll
            for (int i = 0; i < 4; i++)
                d_q[(ty*4 + i) * H3 + c0 + tx] = acc[i];
        }
        grid_bar();

        // ---- Phase 2: attention (both encoders)
        {
            int b = blk & 63, e = blk >> 6;
            const float* P   = d_P[e] + (size_t)(b * NS) * H3;
            const float* enc = d_enc[e] + (size_t)(b * NS) * H2;
            for (int j2 = tid; j2 < H3; j2 += 256) {
                qs[j2]  = __ldcg(&d_q[b * H3 + j2]);
                w2s[j2] = att_W2[j2];
            }
            __syncthreads();
            int w = tid >> 5, lane = tid & 31;
            float b2v = att_b2[0];
#pragma unroll
            for (int si = 0; si < 8; si++) {
                int s = w * 8 + si;
                const float* Pr = P + (size_t)s * H3;
                float part = 0.f;
                for (int j2 = lane; j2 < H3; j2 += 32)
                    part += fmaxf(Pr[j2] + qs[j2], 0.f) * w2s[j2];
#pragma unroll
                for (int off = 16; off; off >>= 1)
                    part += __shfl_down_sync(0xffffffffu, part, off);
                if (lane == 0) logits[s] = part + b2v;
            }
            __syncthreads();
            if (tid == 0) {
                float mx = -1e30f;
                for (int s = 0; s < NS; s++) mx = fmaxf(mx, logits[s]);
                sred[0] = mx;
            }
            __syncthreads();
            if (tid < NS) wts[tid] = expf(logits[tid] - sred[0]);
            __syncthreads();
            if (tid == 0) {
                float sm = 0.f;
                for (int s = 0; s < NS; s++) sm += wts[s];
                sred[1] = 1.f / sm;
            }
            __syncthreads();
            float inv = sred[1];
            float* outA = d_Abuf[e] + (size_t)(t * NB + b) * H2;
            for (int ch = tid; ch < H2; ch += 256) {
                float a = 0.f;
                for (int s = 0; s < NS; s++)
                    a += wts[s] * enc[(size_t)s * H2 + ch];
                outA[ch] = a * inv;
            }
        }
        grid_bar();

        // ---- Phase 3: dec gemm partials: [A,Ar,h] @ [Wih[512:],Whh], K split x4
        {
            int ks = blk >> 5, ct = blk & 31;
            int c0 = ct * 64;
            const float* Ab  = d_Abuf[0] + (size_t)(t * NB) * H2;
            const float* Arb = d_Abuf[1] + (size_t)(t * NB) * H2;
            float acc[4][4];
#pragma unroll
            for (int i = 0; i < 4; i++)
#pragma unroll
                for (int j = 0; j < 4; j++) acc[i][j] = 0.f;

            int k0 = ks * 640;
            for (int kb = k0; kb < k0 + 640; kb += 16) {
                const float* asrc; int stride, koff;
                if (kb < 1024)      { asrc = Ab;  stride = H2; koff = kb; }
                else if (kb < 2048) { asrc = Arb; stride = H2; koff = kb - 1024; }
                else                { asrc = h;   stride = NH; koff = kb - 2048; }
                float4 va = __ldcg((const float4*)(asrc + (size_t)aRow * stride + koff + aCol));
                As[aCol+0][aRow] = va.x; As[aCol+1][aRow] = va.y;
                As[aCol+2][aRow] = va.z; As[aCol+3][aRow] = va.w;
                int kk = kb + (tid >> 4);
                const float* Brow = (kk < 2048) ? (dec_Wih + (size_t)(NE + kk) * H4)
                                                : (dec_Whh + (size_t)(kk - 2048) * H4);
                *(float4*)&Bs[tid >> 4][tx * 4] = *(const float4*)(Brow + c0 + tx * 4);
                __syncthreads();
#pragma unroll
                for (int k = 0; k < 16; k++) {
                    float a[4], b[4];
                    *(float4*)a = *(float4*)&As[k][ty*4];
                    *(float4*)b = *(float4*)&Bs[k][tx*4];
#pragma unroll
                    for (int i = 0; i < 4; i++)
#pragma unroll
                        for (int j = 0; j < 4; j++) acc[i][j] = fmaf(a[i], b[j], acc[i][j]);
                }
                __syncthreads();
            }
            float* gp = d_gpart + (size_t)(ks * NB) * H4;
#pragma unroll
            for (int i = 0; i < 4; i++)
                *(float4*)(gp + (size_t)(ty*4 + i) * H4 + c0 + tx*4) = *(float4*)&acc[i][0];
        }
        grid_bar();

        // ---- Phase 4: gates (1 thread per (m,j))
        {
            const float* xr = d_tgtW + (size_t)(t * NB + pm) * H4;
            float g4[4];
#pragma unroll
            for (int g = 0; g < 4; g++) {
                float v = xr[g * NH + pj];
#pragma unroll
                for (int ks = 0; ks < 4; ks++)
                    v += __ldcg(&d_gpart[(size_t)(ks * NB + pm) * H4 + g * NH + pj]);
                g4[g] = v;
            }
            float cn = sigf(g4[1]) * c_reg + sigf(g4[0]) * tanhf(g4[2]);
            float hv = sigf(g4[3]) * tanhf(cn);
            c_reg = cn;
            d_hdec[(t + 1) & 1][pm * NH + pj] = hv;
            d_Dbuf[((size_t)t * NB + pm) * NH + pj] = hv;
        }
        grid_bar();
    }
}

// ---------------------------------------------------------------------------
// Assemble classifier input ci[r=b*T+t] = [tgt_e, A, Ar, g, D] (zeros past STEPS)
// ---------------------------------------------------------------------------
__global__ void assemble_kernel(const float* __restrict__ graph_embs) {
    int r = blockIdx.x;
    int b = r >> 6, t = r & 63;
    float* row = d_ci + (size_t)r * CIW;
    bool live = (t < NSTEPS);
    for (int c = threadIdx.x; c < CIW; c += 256) {
        float v;
        if (c < 512)       v = d_tgt_e[((size_t)t * NB + b) * NE + c];
        else if (c < 1536) v = live ? d_Abuf[0][((size_t)t * NB + b) * H2 + (c - 512)]  : 0.f;
        else if (c < 2560) v = live ? d_Abuf[1][((size_t)t * NB + b) * H2 + (c - 1536)] : 0.f;
        else if (c < 2816) v = graph_embs[b * NG + (c - 2560)];
        else               v = live ? d_Dbuf[((size_t)t * NB + b) * NH + (c - 2816)]    : 0.f;
        row[c] = v;
    }
}

// ---------------------------------------------------------------------------
// Host launch
// ---------------------------------------------------------------------------
static float* symaddr(const void* s) {
    void* p = nullptr;
    cudaGetSymbolAddress(&p, s);
    return (float*)p;
}

static void gemm_mma(const float* A, const float* B, const float* bias, float* C,
                     int M, int N, int K, int lda, int ldb, int ldc, int relu) {
    dim3 g(M / 128, N / 128);   // x = M tiles (adjacent CTAs share the B band)
    mma_gemm_kernel<<<g, 256, MMAG_SMEM>>>(A, B, bias, C, M, N, K, lda, ldb, ldc, relu);
}

extern "C" void kernel_launch(void* const* d_in, const int* in_sizes, int n_in,
                              void* d_out, int out_size) {
    const int*   source_data = (const int*)d_in[0];
    const int*   target_data = (const int*)d_in[1];
    const int*   rationales  = (const int*)d_in[2];
    const float* graph_embs  = (const float*)d_in[3];
    const float* src_emb     = (const float*)d_in[4];
    const float* tgt_emb     = (const float*)d_in[5];
    const float* enc_Wih_f   = (const float*)d_in[6];
    const float* enc_Whh_f   = (const float*)d_in[7];
    const float* enc_b_f     = (const float*)d_in[8];
    const float* enc_Wih_b   = (const float*)d_in[9];
    const float* enc_Whh_b   = (const float*)d_in[10];
    const float* enc_b_b     = (const float*)d_in[11];
    const float* dec_Wih     = (const float*)d_in[12];
    const float* dec_Whh     = (const float*)d_in[13];
    const float* dec_b       = (const float*)d_in[14];
    const float* att_W1      = (const float*)d_in[15];
    const float* att_b1      = (const float*)d_in[16];
    const float* att_W2      = (const float*)d_in[17];
    const float* att_b2      = (const float*)d_in[18];
    const float* cls_Wg      = (const float*)d_in[19];
    const float* cls_bg      = (const float*)d_in[20];
    const float* cls_W2      = (const float*)d_in[21];
    const float* cls_b2      = (const float*)d_in[22];
    float* out = (float*)d_out;

    cudaFuncSetAttribute(mma_gemm_kernel,
                         cudaFuncAttributeMaxDynamicSharedMemorySize, MMAG_SMEM);

    float* p_src_e = symaddr(d_src_e);
    float* p_rat_e = symaddr(d_rat_e);
    float* p_tgt_e = symaddr(d_tgt_e);
    float* p_Xw    = symaddr(d_Xw);
    float* p_enc   = symaddr(d_enc);
    float* p_P     = symaddr(d_P);
    float* p_tgtW  = symaddr(d_tgtW);
    float* p_ci    = symaddr(d_ci);
    float* p_hid   = symaddr(d_hid);
    void*  p_bar   = nullptr;
    cudaGetSymbolAddress(&p_bar, g_bar);

    const size_t XW  = (size_t)NS * NB * H4;
    const size_t ENC = (size_t)NB * NS * H2;
    const size_t PP  = (size_t)NB * NS * H3;

    cudaMemsetAsync(p_bar, 0, sizeof(unsigned int));
    zero_state_kernel<<<1024, 256>>>();
    gather_kernel<<<dim3(4096, 3), 256>>>(source_data, target_data, rationales,
                                          src_emb, tgt_emb);

    // x @ Wih + b, hoisted for all 4 encoder LSTMs (tf32 mma)
    gemm_mma(p_src_e, enc_Wih_f, enc_b_f, p_Xw + 0*XW, 4096, H4, NE, NE, H4, H4, 0);
    gemm_mma(p_src_e, enc_Wih_b, enc_b_b, p_Xw + 1*XW, 4096, H4, NE, NE, H4, H4, 0);
    gemm_mma(p_rat_e, enc_Wih_f, enc_b_f, p_Xw + 2*XW, 4096, H4, NE, NE, H4, H4, 0);
    gemm_mma(p_rat_e, enc_Wih_b, enc_b_b, p_Xw + 3*XW, 4096, H4, NE, NE, H4, H4, 0);

    // tgt_e @ dec_Wih[:E] + dec_b, hoisted for all 32 decoder steps
    gemm_mma(p_tgt_e, dec_Wih, dec_b, p_tgtW, NSTEPS * NB, H4, NE, NE, H4, H4, 0);

    // encoder recurrence: one persistent kernel, 64 steps
    enc_persistent_kernel<<<GRID_PERS, 256>>>(enc_Whh_f, enc_Whh_b);

    // attention pre-projection: enc_out @ W1[:2H] + b1
    gemm_mma(p_enc + 0*ENC, att_W1, att_b1, p_P + 0*PP, 4096, H3, H2, H2, H3, H3, 0);
    gemm_mma(p_enc + 1*ENC, att_W1, att_b1, p_P + 1*PP, 4096, H3, H2, H2, H3, H3, 0);

    // decoder recurrence: one persistent kernel, 32 steps
    dec_persistent_kernel<<<GRID_PERS, 256>>>(dec_Wih, dec_Whh,
                                              att_W1, att_W2, att_b2);

    // classifier (tf32 mma)
    assemble_kernel<<<4096, 256>>>(graph_embs);
    gemm_mma(p_ci,  cls_Wg, cls_bg, p_hid, 4096, H2, CIW, CIW, H2, H2, 1);
    gemm_mma(p_hid, cls_W2, cls_b2, out,   4096, NV,  H2,  H2, NV, NV, 0);
}

// round 8
// speedup vs baseline: 3.3243x; 1.2296x over previous
#include <cuda_runtime.h>
#include <math.h>
#include <stdint.h>

// ---------------------------------------------------------------------------
// Problem constants: B=64, S=64, T=64, STEPS=32, E=512, H=512, G=256, V=32000
// ---------------------------------------------------------------------------
#define NB   64
#define NS   64
#define NT   64
#define NSTEPS 32
#define NE   512
#define NH   512
#define NG   256
#define NV   32000
#define H4   2048
#define H2   1024
#define H3   1536
#define CIW  3328   // E + 2H + 2H + G + H

#define GRID_PERS 128   // persistent-kernel grid (<=148 SMs -> co-resident)

// ---------------------------------------------------------------------------
// Scratch (device globals; no allocations allowed)
// ---------------------------------------------------------------------------
__device__ float d_src_e[NS*NB*NE];        // time-major [s][b][e]
__device__ float d_rat_e[NS*NB*NE];
__device__ float d_tgt_e[NT*NB*NE];        // [t][b][e]
__device__ float d_Xw[4][NS*NB*H4];        // x@Wih + b per lstm {srcF,srcB,ratF,ratB}
__device__ float d_hbuf[2][4][NB*NH];      // ping-pong h (encoder)
__device__ float d_enc[2][NB*NS*H2];       // [b][s][2H]; 0=src 1=rat
__device__ float d_P[2][NB*NS*H3];         // enc_out @ W1[:2H] + b1
__device__ float d_q[NB*H3];               // h @ W1[2H:]
__device__ float d_Abuf[2][NSTEPS*NB*H2];  // attention outputs A, Ar
__device__ float d_Dbuf[NSTEPS*NB*NH];     // decoder h per step
__device__ float d_tgtW[NSTEPS*NB*H4];     // tgt_e @ dec_Wih[:E] + dec_b
__device__ float d_hdec[2][NB*NH];
__device__ float d_cfin[NB*NH];            // encoder (src,fwd) final c
__device__ float d_gpart[4*NB*H4];         // decoder gemm K-split partials
__device__ float d_ci[(size_t)NB*NT*CIW];
__device__ float d_hid[(size_t)NB*NT*H2];
// fragment-packed tf32 operand scratch
__device__ uint32_t d_Ap[16*1024*1024];    // 64MB: slot0 @0, slot1 @8M
__device__ uint32_t d_Bp[(size_t)H2*NV];   // 131MB (max = cls_W2)
__device__ unsigned int g_bar = 0;

#define AP_SLOT1 (8u*1024u*1024u)

__device__ __forceinline__ float sigf(float x) { return 1.f / (1.f + expf(-x)); }

// Software grid barrier. All GRID_PERS blocks must be co-resident.
__device__ __forceinline__ void grid_bar() {
    __syncthreads();
    if (threadIdx.x == 0) {
        __threadfence();                       // release
        unsigned int t = atomicAdd(&g_bar, 1u);
        unsigned int target = t - (t & (GRID_PERS - 1u)) + GRID_PERS;
        unsigned int v;
        do {
            asm volatile("ld.acquire.gpu.global.u32 %0, [%1];"
                         : "=r"(v) : "l"(&g_bar) : "memory");
        } while (v < target);
    }
    __syncthreads();
}

__device__ __forceinline__ uint32_t f2tf32(float f) {
    uint32_t r;
    asm("cvt.rna.tf32.f32 %0, %1;" : "=r"(r) : "f"(f));
    return r;
}

// ---------------------------------------------------------------------------
// Operand pack kernels: permute fp32 [M,K]/[K,N] into fragment-ordered tf32.
// A pack: uint4 per (ks, mslot, lane(g,t)) = {A[m0][k0], A[m0+8][k0],
//         A[m0][k0+4], A[m0+8][k0+4]}, m0=mslot*16+g, k0=ks*8+t.
// B pack: uint4 per (ks, npair, lane(g,t)) = {B[k0][n0], B[k0+4][n0],
//         B[k0][n0+8], B[k0+4][n0+8]}, n0=npair*16+g.
// ---------------------------------------------------------------------------
__global__ void packA_kernel(const float* __restrict__ A, uint32_t* __restrict__ Ap,
                             int M, int K, int lda) {
    int idx = blockIdx.x * 256 + threadIdx.x;          // one uint4 per thread
    int total = (K >> 3) * (M >> 4) * 32;
    if (idx >= total) return;
    int lane = idx & 31;
    int g = lane >> 2, t = lane & 3;
    int rest = idx >> 5;
    int MS = M >> 4;
    int mslot = rest % MS, ks = rest / MS;
    int m0 = mslot * 16 + g, k0 = ks * 8 + t;
    uint4 u;
    u.x = f2tf32(A[(size_t)m0 * lda + k0]);
    u.y = f2tf32(A[(size_t)(m0 + 8) * lda + k0]);
    u.z = f2tf32(A[(size_t)m0 * lda + k0 + 4]);
    u.w = f2tf32(A[(size_t)(m0 + 8) * lda + k0 + 4]);
    ((uint4*)Ap)[idx] = u;
}

__global__ void packB_kernel(const float* __restrict__ B, uint32_t* __restrict__ Bp,
                             int K, int N, int ldb) {
    int idx = blockIdx.x * 256 + threadIdx.x;
    int total = (K >> 3) * (N >> 4) * 32;
    if (idx >= total) return;
    int lane = idx & 31;
    int g = lane >> 2, t = lane & 3;
    int rest = idx >> 5;
    int NP = N >> 4;
    int npair = rest % NP, ks = rest / NP;
    int n0 = npair * 16 + g, k0 = ks * 8 + t;
    uint4 u;
    u.x = f2tf32(B[(size_t)k0 * ldb + n0]);
    u.y = f2tf32(B[(size_t)(k0 + 4) * ldb + n0]);
    u.z = f2tf32(B[(size_t)k0 * ldb + n0 + 8]);
    u.w = f2tf32(B[(size_t)(k0 + 4) * ldb + n0 + 8]);
    ((uint4*)Bp)[idx] = u;
}

// ---------------------------------------------------------------------------
// Packed tf32 mma.sync GEMM: C[M,N] = A@B (+bias)(+relu).
// Operands fragment-packed in global (L1-cached, LDG.128 per frag).
// No smem, no syncthreads. 256 threads = 8 warps (2m x 4n), warp 64x32.
// 2-deep register pipeline over K-steps of 8. M%128==0, N%128==0, K%16==0.
// ---------------------------------------------------------------------------
#define MMA16(accv, av, b0, b1)                                               \
    asm volatile(                                                             \
        "mma.sync.aligned.m16n8k8.row.col.f32.tf32.tf32.f32 "                 \
        "{%0,%1,%2,%3}, {%4,%5,%6,%7}, {%8,%9}, {%0,%1,%2,%3};"               \
        : "+f"((accv)[0]), "+f"((accv)[1]), "+f"((accv)[2]), "+f"((accv)[3])  \
        : "r"((av).x), "r"((av).y), "r"((av).z), "r"((av).w),                 \
          "r"(b0), "r"(b1))

__global__ void __launch_bounds__(256, 2)
mma_gemm_pk(const uint32_t* __restrict__ Ap, const uint32_t* __restrict__ Bp,
            const float* __restrict__ bias, float* __restrict__ C,
            int M, int N, int K, int relu) {
    int tid = threadIdx.x;
    int wid = tid >> 5, lane = tid & 31;
    int warp_m = wid & 1, warp_n = wid >> 1;
    int g = lane >> 2, t = lane & 3;
    int row0 = blockIdx.x * 128, col0 = blockIdx.y * 128;
    int MS = M >> 4, NP = N >> 4;
    int KS = K >> 3;                      // even for all our shapes

    const uint4* A4 = (const uint4*)Ap + (size_t)((row0 >> 4) + warp_m * 4) * 32 + lane;
    const uint4* B4 = (const uint4*)Bp + (size_t)((col0 >> 4) + warp_n * 2) * 32 + lane;
    size_t aStep = (size_t)MS * 32;
    size_t bStep = (size_t)NP * 32;

    float acc[4][4][4];
#pragma unroll
    for (int i = 0; i < 4; i++)
#pragma unroll
        for (int j = 0; j < 4; j++)
#pragma unroll
            for (int f = 0; f < 4; f++) acc[i][j][f] = 0.f;

    uint4 pa0[4], pb0[2], pa1[4], pb1[2];
#pragma unroll
    for (int mt = 0; mt < 4; mt++) pa0[mt] = A4[mt * 32];
#pragma unroll
    for (int np = 0; np < 2; np++) pb0[np] = B4[np * 32];

    for (int ks = 0; ks < KS; ks += 2) {
        {   // prefetch ks+1 into set 1 (overlaps with mma on set 0)
            const uint4* An = A4 + (size_t)(ks + 1) * aStep;
            const uint4* Bn = B4 + (size_t)(ks + 1) * bStep;
#pragma unroll
            for (int mt = 0; mt < 4; mt++) pa1[mt] = An[mt * 32];
#pragma unroll
            for (int np = 0; np < 2; np++) pb1[np] = Bn[np * 32];
        }
#pragma unroll
        for (int mt = 0; mt < 4; mt++) {
            MMA16(acc[mt][0], pa0[mt], pb0[0].x, pb0[0].y);
            MMA16(acc[mt][1], pa0[mt], pb0[0].z, pb0[0].w);
            MMA16(acc[mt][2], pa0[mt], pb0[1].x, pb0[1].y);
            MMA16(acc[mt][3], pa0[mt], pb0[1].z, pb0[1].w);
        }
        if (ks + 2 < KS) {  // prefetch ks+2 into set 0
            const uint4* An = A4 + (size_t)(ks + 2) * aStep;
            const uint4* Bn = B4 + (size_t)(ks + 2) * bStep;
#pragma unroll
            for (int mt = 0; mt < 4; mt++) pa0[mt] = An[mt * 32];
#pragma unroll
            for (int np = 0; np < 2; np++) pb0[np] = Bn[np * 32];
        }
#pragma unroll
        for (int mt = 0; mt < 4; mt++) {
            MMA16(acc[mt][0], pa1[mt], pb1[0].x, pb1[0].y);
            MMA16(acc[mt][1], pa1[mt], pb1[0].z, pb1[0].w);
            MMA16(acc[mt][2], pa1[mt], pb1[1].x, pb1[1].y);
            MMA16(acc[mt][3], pa1[mt], pb1[1].z, pb1[1].w);
        }
    }

    // epilogue
#pragma unroll
    for (int mt = 0; mt < 4; mt++) {
        int r = row0 + warp_m * 64 + mt * 16 + g;
#pragma unroll
        for (int j = 0; j < 4; j++) {
            int cc = col0 + warp_n * 32 + j * 8 + t * 2;
            float2 v0, v1;
            v0.x = acc[mt][j][0]; v0.y = acc[mt][j][1];
            v1.x = acc[mt][j][2]; v1.y = acc[mt][j][3];
            if (bias) {
                float b0 = bias[cc], b1 = bias[cc + 1];
                v0.x += b0; v0.y += b1; v1.x += b0; v1.y += b1;
            }
            if (relu) {
                v0.x = fmaxf(v0.x, 0.f); v0.y = fmaxf(v0.y, 0.f);
                v1.x = fmaxf(v1.x, 0.f); v1.y = fmaxf(v1.y, 0.f);
            }
            *(float2*)(C + (size_t)r * N + cc) = v0;
            *(float2*)(C + (size_t)(r + 8) * N + cc) = v1;
        }
    }
}

// ---------------------------------------------------------------------------
// Zero / gather
// ---------------------------------------------------------------------------
__global__ void zero_state_kernel() {
    int i = blockIdx.x * 256 + threadIdx.x;
    if (i < 2*4*NB*NH) ((float*)d_hbuf)[i] = 0.f;
}

__global__ void gather_kernel(const int* __restrict__ src_ids,
                              const int* __restrict__ tgt_ids,
                              const int* __restrict__ rat_ids,
                              const float* __restrict__ src_emb,
                              const float* __restrict__ tgt_emb) {
    int tok = blockIdx.x;          // s*64 + b
    int set = blockIdx.y;          // 0 src, 1 rat, 2 tgt
    int s = tok >> 6, b = tok & 63;
    int id;
    const float* emb;
    float* out;
    if (set == 0)      { id = src_ids[b*NS + s]; emb = src_emb; out = d_src_e; }
    else if (set == 1) { id = rat_ids[b*NS + s]; emb = src_emb; out = d_rat_e; }
    else               { id = tgt_ids[b*NT + s]; emb = tgt_emb; out = d_tgt_e; }
    const float* row = emb + (size_t)id * NE;
    float* dst = out + (size_t)tok * NE;
    for (int e = threadIdx.x; e < NE; e += 256) dst[e] = row[e];
}

// ---------------------------------------------------------------------------
// Persistent encoder: all 64 steps, 4 LSTMs, one kernel. (unchanged)
// ---------------------------------------------------------------------------
__global__ void __launch_bounds__(256)
enc_persistent_kernel(const float* __restrict__ Whh_f,
                      const float* __restrict__ Whh_b) {
    __shared__ float As[16][64];
    __shared__ float Bs[16][68];
    __shared__ float gsm[64][68];
    __shared__ float cs[64][16];
    int blk = blockIdx.x;
    int l = blk >> 5;                 // lstm id {srcF,srcB,ratF,ratB}
    int j0 = (blk & 31) * 16;         // unit-tile base
    const float* Whh = (l & 1) ? Whh_b : Whh_f;
    int tid = threadIdx.x;
    int tx = tid & 15, ty = tid >> 4;

    for (int p = tid; p < 1024; p += 256) ((float*)cs)[p] = 0.f;

    int aRow = tid >> 2, aCol = (tid & 3) * 4;
    int bRow = tid >> 4, bCol = tx * 4;
    const float* Bbase = Whh + (bCol >> 4) * NH + j0 + (bCol & 15);

    float* eo = (l < 2) ? d_enc[0] : d_enc[1];
    int half = (l & 1) * NH;

    for (int t = 0; t < NS; t++) {
        const float* h = d_hbuf[t & 1][l];
        float acc[4][4];
#pragma unroll
        for (int i = 0; i < 4; i++)
#pragma unroll
            for (int j = 0; j < 4; j++) acc[i][j] = 0.f;

        for (int kb = 0; kb < NH; kb += 16) {
            float4 va = __ldcg((const float4*)(h + aRow * NH + kb + aCol));
            As[aCol+0][aRow] = va.x; As[aCol+1][aRow] = va.y;
            As[aCol+2][aRow] = va.z; As[aCol+3][aRow] = va.w;
            float4 vb = *(const float4*)(Bbase + (size_t)(kb + bRow) * H4);
            *(float4*)&Bs[bRow][bCol] = vb;
            __syncthreads();
#pragma unroll
            for (int k = 0; k < 16; k++) {
                float a[4], b[4];
                *(float4*)a = *(float4*)&As[k][ty*4];
                *(float4*)b = *(float4*)&Bs[k][tx*4];
#pragma unroll
                for (int i = 0; i < 4; i++)
#pragma unroll
                    for (int j = 0; j < 4; j++) acc[i][j] = fmaf(a[i], b[j], acc[i][j]);
            }
            __syncthreads();
        }
#pragma unroll
        for (int i = 0; i < 4; i++)
            *(float4*)&gsm[ty*4 + i][tx*4] = *(float4*)&acc[i][0];
        __syncthreads();

        int tX = (l & 1) ? (NS - 1 - t) : t;
        const float* xw = d_Xw[l] + (size_t)(tX * NB) * H4;
        float* hn = d_hbuf[(t + 1) & 1][l];
        for (int p = tid; p < 1024; p += 256) {
            int m = p >> 4, jj = p & 15;
            int j = j0 + jj;
            const float* xr = xw + (size_t)m * H4;
            float gi = gsm[m][jj]      + xr[j];
            float gf = gsm[m][16 + jj] + xr[NH + j];
            float gg = gsm[m][32 + jj] + xr[2*NH + j];
            float go = gsm[m][48 + jj] + xr[3*NH + j];
            float cp = cs[m][jj];
            float cn = sigf(gf) * cp + sigf(gi) * tanhf(gg);
            float hv = sigf(go) * tanhf(cn);
            cs[m][jj] = cn;
            hn[m*NH + j] = hv;
            eo[((size_t)m * NS + tX) * H2 + half + j] = hv;
        }
        grid_bar();
    }
    // dump (src,fwd) final c for decoder init
    if (l == 0) {
        for (int p = tid; p < 1024; p += 256) {
            int m = p >> 4, jj = p & 15;
            d_cfin[m*NH + j0 + jj] = cs[m][jj];
        }
    }
}

// ---------------------------------------------------------------------------
// Persistent decoder: all 32 steps, one kernel, 4 phases/step. (unchanged)
// ---------------------------------------------------------------------------
__global__ void __launch_bounds__(256)
dec_persistent_kernel(const float* __restrict__ dec_Wih,
                      const float* __restrict__ dec_Whh,
                      const float* __restrict__ att_W1,
                      const float* __restrict__ att_W2,
                      const float* __restrict__ att_b2) {
    __shared__ float As[16][64];
    __shared__ float Bs[16][68];
    __shared__ float Bq[16][17];
    __shared__ float qs[H3];
    __shared__ float w2s[H3];
    __shared__ float logits[NS];
    __shared__ float wts[NS];
    __shared__ float sred[2];

    int blk = blockIdx.x, tid = threadIdx.x;
    int tx = tid & 15, ty = tid >> 4;
    int aRow = tid >> 2, aCol = (tid & 3) * 4;

    int p = blk * 256 + tid;           // 0..32767
    int pm = p >> 9, pj = p & 511;
    float c_reg = d_cfin[pm * NH + pj];

    for (int t = 0; t < NSTEPS; t++) {
        const float* h = (t == 0) ? d_hbuf[0][0] : d_hdec[t & 1];

        // ---- Phase 1: q[64,1536] = h[64,512] @ W1[1024:1536, :]
        if (blk < 96) {
            int c0 = blk * 16;
            float acc[4] = {0.f, 0.f, 0.f, 0.f};
            for (int kb = 0; kb < NH; kb += 16) {
                float4 va = __ldcg((const float4*)(h + aRow * NH + kb + aCol));
                As[aCol+0][aRow] = va.x; As[aCol+1][aRow] = va.y;
                As[aCol+2][aRow] = va.z; As[aCol+3][aRow] = va.w;
                Bq[tid >> 4][tid & 15] =
                    att_W1[(size_t)(H2 + kb + (tid >> 4)) * H3 + c0 + (tid & 15)];
                __syncthreads();
#pragma unroll
                for (int k = 0; k < 16; k++) {
                    float b = Bq[k][tx];
#pragma unroll
                    for (int i = 0; i < 4; i++)
                        acc[i] = fmaf(As[k][ty*4 + i], b, acc[i]);
                }
                __syncthreads();
            }
#pragma unroll
            for (int i = 0; i < 4; i++)
                d_q[(ty*4 + i) * H3 + c0 + tx] = acc[i];
        }
        grid_bar();

        // ---- Phase 2: attention (both encoders)
        {
            int b = blk & 63, e = blk >> 6;
            const float* P   = d_P[e] + (size_t)(b * NS) * H3;
            const float* enc = d_enc[e] + (size_t)(b * NS) * H2;
            for (int j2 = tid; j2 < H3; j2 += 256) {
                qs[j2]  = __ldcg(&d_q[b * H3 + j2]);
                w2s[j2] = att_W2[j2];
            }
            __syncthreads();
            int w = tid >> 5, lane = tid & 31;
            float b2v = att_b2[0];
#pragma unroll
            for (int si = 0; si < 8; si++) {
                int s = w * 8 + si;
                const float* Pr = P + (size_t)s * H3;
                float part = 0.f;
                for (int j2 = lane; j2 < H3; j2 += 32)
                    part += fmaxf(Pr[j2] + qs[j2], 0.f) * w2s[j2];
#pragma unroll
                for (int off = 16; off; off >>= 1)
                    part += __shfl_down_sync(0xffffffffu, part, off);
                if (lane == 0) logits[s] = part + b2v;
            }
            __syncthreads();
            if (tid == 0) {
                float mx = -1e30f;
                for (int s = 0; s < NS; s++) mx = fmaxf(mx, logits[s]);
                sred[0] = mx;
            }
            __syncthreads();
            if (tid < NS) wts[tid] = expf(logits[tid] - sred[0]);
            __syncthreads();
            if (tid == 0) {
                float sm = 0.f;
                for (int s = 0; s < NS; s++) sm += wts[s];
                sred[1] = 1.f / sm;
            }
            __syncthreads();
            float inv = sred[1];
            float* outA = d_Abuf[e] + (size_t)(t * NB + b) * H2;
            for (int ch = tid; ch < H2; ch += 256) {
                float a = 0.f;
                for (int s = 0; s < NS; s++)
                    a += wts[s] * enc[(size_t)s * H2 + ch];
                outA[ch] = a * inv;
            }
        }
        grid_bar();

        // ---- Phase 3: dec gemm partials: [A,Ar,h] @ [Wih[512:],Whh], K split x4
        {
            int ks = blk >> 5, ct = blk & 31;
            int c0 = ct * 64;
            const float* Ab  = d_Abuf[0] + (size_t)(t * NB) * H2;
            const float* Arb = d_Abuf[1] + (size_t)(t * NB) * H2;
            float acc[4][4];
#pragma unroll
            for (int i = 0; i < 4; i++)
#pragma unroll
                for (int j = 0; j < 4; j++) acc[i][j] = 0.f;

            int k0 = ks * 640;
            for (int kb = k0; kb < k0 + 640; kb += 16) {
                const float* asrc; int stride, koff;
                if (kb < 1024)      { asrc = Ab;  stride = H2; koff = kb; }
                else if (kb < 2048) { asrc = Arb; stride = H2; koff = kb - 1024; }
                else                { asrc = h;   stride = NH; koff = kb - 2048; }
                float4 va = __ldcg((const float4*)(asrc + (size_t)aRow * stride + koff + aCol));
                As[aCol+0][aRow] = va.x; As[aCol+1][aRow] = va.y;
                As[aCol+2][aRow] = va.z; As[aCol+3][aRow] = va.w;
                int kk = kb + (tid >> 4);
                const float* Brow = (kk < 2048) ? (dec_Wih + (size_t)(NE + kk) * H4)
                                                : (dec_Whh + (size_t)(kk - 2048) * H4);
                *(float4*)&Bs[tid >> 4][tx * 4] = *(const float4*)(Brow + c0 + tx * 4);
                __syncthreads();
#pragma unroll
                for (int k = 0; k < 16; k++) {
                    float a[4], b[4];
                    *(float4*)a = *(float4*)&As[k][ty*4];
                    *(float4*)b = *(float4*)&Bs[k][tx*4];
#pragma unroll
                    for (int i = 0; i < 4; i++)
#pragma unroll
                        for (int j = 0; j < 4; j++) acc[i][j] = fmaf(a[i], b[j], acc[i][j]);
                }
                __syncthreads();
            }
            float* gp = d_gpart + (size_t)(ks * NB) * H4;
#pragma unroll
            for (int i = 0; i < 4; i++)
                *(float4*)(gp + (size_t)(ty*4 + i) * H4 + c0 + tx*4) = *(float4*)&acc[i][0];
        }
        grid_bar();

        // ---- Phase 4: gates (1 thread per (m,j))
        {
            const float* xr = d_tgtW + (size_t)(t * NB + pm) * H4;
            float g4[4];
#pragma unroll
            for (int g = 0; g < 4; g++) {
                float v = xr[g * NH + pj];
#pragma unroll
                for (int ks = 0; ks < 4; ks++)
                    v += __ldcg(&d_gpart[(size_t)(ks * NB + pm) * H4 + g * NH + pj]);
                g4[g] = v;
            }
            float cn = sigf(g4[1]) * c_reg + sigf(g4[0]) * tanhf(g4[2]);
            float hv = sigf(g4[3]) * tanhf(cn);
            c_reg = cn;
            d_hdec[(t + 1) & 1][pm * NH + pj] = hv;
            d_Dbuf[((size_t)t * NB + pm) * NH + pj] = hv;
        }
        grid_bar();
    }
}

// ---------------------------------------------------------------------------
// Assemble classifier input ci[r=b*T+t] = [tgt_e, A, Ar, g, D] (zeros past STEPS)
// ---------------------------------------------------------------------------
__global__ void assemble_kernel(const float* __restrict__ graph_embs) {
    int r = blockIdx.x;
    int b = r >> 6, t = r & 63;
    float* row = d_ci + (size_t)r * CIW;
    bool live = (t < NSTEPS);
    for (int c = threadIdx.x; c < CIW; c += 256) {
        float v;
        if (c < 512)       v = d_tgt_e[((size_t)t * NB + b) * NE + c];
        else if (c < 1536) v = live ? d_Abuf[0][((size_t)t * NB + b) * H2 + (c - 512)]  : 0.f;
        else if (c < 2560) v = live ? d_Abuf[1][((size_t)t * NB + b) * H2 + (c - 1536)] : 0.f;
        else if (c < 2816) v = graph_embs[b * NG + (c - 2560)];
        else               v = live ? d_Dbuf[((size_t)t * NB + b) * NH + (c - 2816)]    : 0.f;
        row[c] = v;
    }
}

// ---------------------------------------------------------------------------
// Host launch
// ---------------------------------------------------------------------------
static float* symaddr(const void* s) {
    void* p = nullptr;
    cudaGetSymbolAddress(&p, s);
    return (float*)p;
}

static void packA(const float* A, uint32_t* Ap, int M, int K, int lda) {
    int total = (K >> 3) * (M >> 4) * 32;
    packA_kernel<<<(total + 255) / 256, 256>>>(A, Ap, M, K, lda);
}
static void packB(const float* B, uint32_t* Bp, int K, int N, int ldb) {
    int total = (K >> 3) * (N >> 4) * 32;
    packB_kernel<<<(total + 255) / 256, 256>>>(B, Bp, K, N, ldb);
}
static void gemm_pk(const uint32_t* Ap, const uint32_t* Bp, const float* bias,
                    float* C, int M, int N, int K, int relu) {
    dim3 g(M / 128, N / 128);   // x = M tiles (adjacent CTAs share the B band)
    mma_gemm_pk<<<g, 256>>>(Ap, Bp, bias, C, M, N, K, relu);
}

extern "C" void kernel_launch(void* const* d_in, const int* in_sizes, int n_in,
                              void* d_out, int out_size) {
    const int*   source_data = (const int*)d_in[0];
    const int*   target_data = (const int*)d_in[1];
    const int*   rationales  = (const int*)d_in[2];
    const float* graph_embs  = (const float*)d_in[3];
    const float* src_emb     = (const float*)d_in[4];
    const float* tgt_emb     = (const float*)d_in[5];
    const float* enc_Wih_f   = (const float*)d_in[6];
    const float* enc_Whh_f   = (const float*)d_in[7];
    const float* enc_b_f     = (const float*)d_in[8];
    const float* enc_Wih_b   = (const float*)d_in[9];
    const float* enc_Whh_b   = (const float*)d_in[10];
    const float* enc_b_b     = (const float*)d_in[11];
    const float* dec_Wih     = (const float*)d_in[12];
    const float* dec_Whh     = (const float*)d_in[13];
    const float* dec_b       = (const float*)d_in[14];
    const float* att_W1      = (const float*)d_in[15];
    const float* att_b1      = (const float*)d_in[16];
    const float* att_W2      = (const float*)d_in[17];
    const float* att_b2      = (const float*)d_in[18];
    const float* cls_Wg      = (const float*)d_in[19];
    const float* cls_bg      = (const float*)d_in[20];
    const float* cls_W2      = (const float*)d_in[21];
    const float* cls_b2      = (const float*)d_in[22];
    float* out = (float*)d_out;

    float* p_src_e = symaddr(d_src_e);
    float* p_rat_e = symaddr(d_rat_e);
    float* p_tgt_e = symaddr(d_tgt_e);
    float* p_Xw    = symaddr(d_Xw);
    float* p_enc   = symaddr(d_enc);
    float* p_P     = symaddr(d_P);
    float* p_tgtW  = symaddr(d_tgtW);
    float* p_ci    = symaddr(d_ci);
    float* p_hid   = symaddr(d_hid);
    uint32_t* p_Ap = (uint32_t*)symaddr(d_Ap);
    uint32_t* p_Bp = (uint32_t*)symaddr(d_Bp);
    void*  p_bar   = nullptr;
    cudaGetSymbolAddress(&p_bar, g_bar);

    const size_t XW  = (size_t)NS * NB * H4;
    const size_t ENC = (size_t)NB * NS * H2;
    const size_t PP  = (size_t)NB * NS * H3;

    cudaMemsetAsync(p_bar, 0, sizeof(unsigned int));
    zero_state_kernel<<<1024, 256>>>();
    gather_kernel<<<dim3(4096, 3), 256>>>(source_data, target_data, rationales,
                                          src_emb, tgt_emb);

    // x @ Wih + b, hoisted for all 4 encoder LSTMs (packed tf32 mma)
    packA(p_src_e, p_Ap,            4096, NE, NE);
    packA(p_rat_e, p_Ap + AP_SLOT1, 4096, NE, NE);
    packB(enc_Wih_f, p_Bp, NE, H4, H4);
    gemm_pk(p_Ap,            p_Bp, enc_b_f, p_Xw + 0*XW, 4096, H4, NE, 0);
    gemm_pk(p_Ap + AP_SLOT1, p_Bp, enc_b_f, p_Xw + 2*XW, 4096, H4, NE, 0);
    packB(enc_Wih_b, p_Bp, NE, H4, H4);
    gemm_pk(p_Ap,            p_Bp, enc_b_b, p_Xw + 1*XW, 4096, H4, NE, 0);
    gemm_pk(p_Ap + AP_SLOT1, p_Bp, enc_b_b, p_Xw + 3*XW, 4096, H4, NE, 0);

    // tgt_e @ dec_Wih[:E] + dec_b, hoisted for all 32 decoder steps
    packA(p_tgt_e, p_Ap, NSTEPS * NB, NE, NE);
    packB(dec_Wih, p_Bp, NE, H4, H4);           // first E rows
    gemm_pk(p_Ap, p_Bp, dec_b, p_tgtW, NSTEPS * NB, H4, NE, 0);

    // encoder recurrence: one persistent kernel, 64 steps
    enc_persistent_kernel<<<GRID_PERS, 256>>>(enc_Whh_f, enc_Whh_b);

    // attention pre-projection: enc_out @ W1[:2H] + b1
    packA(p_enc + 0*ENC, p_Ap,            4096, H2, H2);
    packA(p_enc + 1*ENC, p_Ap + AP_SLOT1, 4096, H2, H2);
    packB(att_W1, p_Bp, H2, H3, H3);            // first 2H rows
    gemm_pk(p_Ap,            p_Bp, att_b1, p_P + 0*PP, 4096, H3, H2, 0);
    gemm_pk(p_Ap + AP_SLOT1, p_Bp, att_b1, p_P + 1*PP, 4096, H3, H2, 0);

    // decoder recurrence: one persistent kernel, 32 steps
    dec_persistent_kernel<<<GRID_PERS, 256>>>(dec_Wih, dec_Whh,
                                              att_W1, att_W2, att_b2);

    // classifier
    assemble_kernel<<<4096, 256>>>(graph_embs);
    packA(p_ci, p_Ap, 4096, CIW, CIW);
    packB(cls_Wg, p_Bp, CIW, H2, H2);
    gemm_pk(p_Ap, p_Bp, cls_bg, p_hid, 4096, H2, CIW, 1);
    packA(p_hid, p_Ap, 4096, H2, H2);
    packB(cls_W2, p_Bp, H2, NV, NV);
    gemm_pk(p_Ap, p_Bp, cls_b2, out, 4096, NV, H2, 0);
}